// round 1
// baseline (speedup 1.0000x reference)
#include <cuda_runtime.h>

#define BB 4
#define C 512
#define D 64
#define HW 4096
#define GROUPS 32
#define CPG 16
#define EPS 1e-5f

// Scratch (device globals — no allocation allowed)
__device__ float g_xn[BB * C * HW];   // normalized x, [B,C,N]
__device__ float g_q[BB * HW * D];    // [B,N,D]
__device__ float g_k[BB * HW * D];    // [B,N,D]
__device__ float g_v[BB * HW * D];    // [B,N,D]
__device__ float g_ao[BB * HW * D];   // attention output [B,N,D]

// ---------------------------------------------------------------------------
// 1. GroupNorm: one block per (b, group). Group = 16 contiguous channels
//    x 4096 spatial = 65536 contiguous floats.
// ---------------------------------------------------------------------------
__global__ void gn_kernel(const float* __restrict__ x,
                          const float* __restrict__ gamma,
                          const float* __restrict__ beta) {
    int bg = blockIdx.x;
    int b = bg / GROUPS, g = bg % GROUPS;
    const float* xp = x + ((size_t)b * C + g * CPG) * HW;
    float* op = g_xn + ((size_t)b * C + g * CPG) * HW;
    const int NE = CPG * HW;  // 65536

    float s = 0.f, ss = 0.f;
    for (int i = threadIdx.x * 4; i < NE; i += blockDim.x * 4) {
        float4 v = *(const float4*)(xp + i);
        s += v.x + v.y + v.z + v.w;
        ss += v.x * v.x + v.y * v.y + v.z * v.z + v.w * v.w;
    }
    __shared__ float sbuf[32], ssbuf[32];
#pragma unroll
    for (int o = 16; o; o >>= 1) {
        s += __shfl_xor_sync(~0u, s, o);
        ss += __shfl_xor_sync(~0u, ss, o);
    }
    int w = threadIdx.x >> 5;
    if ((threadIdx.x & 31) == 0) { sbuf[w] = s; ssbuf[w] = ss; }
    __syncthreads();
    int nw = blockDim.x >> 5;
    if (threadIdx.x < 32) {
        s = threadIdx.x < nw ? sbuf[threadIdx.x] : 0.f;
        ss = threadIdx.x < nw ? ssbuf[threadIdx.x] : 0.f;
#pragma unroll
        for (int o = 16; o; o >>= 1) {
            s += __shfl_xor_sync(~0u, s, o);
            ss += __shfl_xor_sync(~0u, ss, o);
        }
        if (threadIdx.x == 0) { sbuf[0] = s; ssbuf[0] = ss; }
    }
    __syncthreads();
    float mean = sbuf[0] / NE;
    float var = ssbuf[0] / NE - mean * mean;
    float rstd = rsqrtf(var + EPS);

    for (int i = threadIdx.x * 4; i < NE; i += blockDim.x * 4) {
        int c = g * CPG + (i >> 12);  // i/HW
        float ga = gamma[c] * rstd;
        float be = beta[c] - mean * ga;
        float4 v = *(const float4*)(xp + i);
        v.x = v.x * ga + be;
        v.y = v.y * ga + be;
        v.z = v.z * ga + be;
        v.w = v.w * ga + be;
        *(float4*)(op + i) = v;
    }
}

// ---------------------------------------------------------------------------
// 2. QKV projection GEMM: out[b][n][d] = sum_c w[d][c] * xn[b][c][n] + bias[d]
//    Tile: 64 n x 64 d per block, K-chunks of 32. 256 threads, 4x4 register
//    tile per thread.  which: 0->q, 1->k, 2->v
// ---------------------------------------------------------------------------
__global__ void proj_kernel(const float* __restrict__ w,
                            const float* __restrict__ bias,
                            int which) {
    __shared__ float xs[32][68];  // [kk][n]
    __shared__ float ws[64][33];  // [d][kk]
    int b = blockIdx.y;
    int n0 = blockIdx.x * 64;
    int tid = threadIdx.x;
    int tx = tid & 15, ty = tid >> 4;
    float* out = (which == 0) ? g_q : (which == 1) ? g_k : g_v;

    float acc[4][4] = {};
    const float* xb = g_xn + (size_t)b * C * HW;

    for (int k0 = 0; k0 < C; k0 += 32) {
#pragma unroll
        for (int i = 0; i < 2; i++) {
            int idx = (tid + i * 256) * 4;
            int kk = idx >> 6, nn = idx & 63;
            *(float4*)&xs[kk][nn] = *(const float4*)&xb[(size_t)(k0 + kk) * HW + n0 + nn];
        }
#pragma unroll
        for (int i = 0; i < 2; i++) {
            int idx = (tid + i * 256) * 4;
            int d = idx >> 5, kk = idx & 31;
            float4 t = *(const float4*)&w[d * C + k0 + kk];
            ws[d][kk] = t.x; ws[d][kk + 1] = t.y; ws[d][kk + 2] = t.z; ws[d][kk + 3] = t.w;
        }
        __syncthreads();
#pragma unroll
        for (int kk = 0; kk < 32; kk++) {
            float4 a4 = *(const float4*)&xs[kk][tx * 4];
            float a[4] = {a4.x, a4.y, a4.z, a4.w};
            float bb[4];
#pragma unroll
            for (int i = 0; i < 4; i++) bb[i] = ws[ty * 4 + i][kk];
#pragma unroll
            for (int i = 0; i < 4; i++)
#pragma unroll
                for (int j = 0; j < 4; j++) acc[i][j] += bb[i] * a[j];
        }
        __syncthreads();
    }
#pragma unroll
    for (int i = 0; i < 4; i++) {
        float bi = bias[ty * 4 + i];
#pragma unroll
        for (int j = 0; j < 4; j++) {
            out[((size_t)b * HW + n0 + tx * 4 + j) * D + ty * 4 + i] = acc[i][j] + bi;
        }
    }
}

// ---------------------------------------------------------------------------
// 3. Attention: one thread per query, online softmax. K/V tiles of 64 keys in
//    shared memory, broadcast-read as float4. Block = 64 threads (64 queries).
// ---------------------------------------------------------------------------
__global__ void attn_kernel() {
    int b = blockIdx.y;
    int n = blockIdx.x * 64 + threadIdx.x;
    const float scale = 0.125f;  // D^-0.5

    __shared__ float Ks[64 * 64];
    __shared__ float Vs[64 * 64];

    float q[64];
    {
        const float4* qp = (const float4*)&g_q[((size_t)b * HW + n) * D];
#pragma unroll
        for (int i = 0; i < 16; i++) {
            float4 t = qp[i];
            q[4 * i + 0] = t.x * scale;
            q[4 * i + 1] = t.y * scale;
            q[4 * i + 2] = t.z * scale;
            q[4 * i + 3] = t.w * scale;
        }
    }
    float o[64];
#pragma unroll
    for (int i = 0; i < 64; i++) o[i] = 0.f;
    float m = -1e30f, l = 0.f;

    const float* kb = g_k + (size_t)b * HW * D;
    const float* vb = g_v + (size_t)b * HW * D;

    for (int t0 = 0; t0 < HW; t0 += 64) {
        __syncthreads();
#pragma unroll
        for (int i = 0; i < 16; i++) {
            int idx = (threadIdx.x + i * 64) * 4;
            *(float4*)&Ks[idx] = *(const float4*)&kb[(size_t)t0 * D + idx];
            *(float4*)&Vs[idx] = *(const float4*)&vb[(size_t)t0 * D + idx];
        }
        __syncthreads();

        for (int jc = 0; jc < 64; jc += 16) {
            float s[16];
            float tmax = -1e30f;
#pragma unroll
            for (int j = 0; j < 16; j++) {
                const float4* kr = (const float4*)&Ks[(jc + j) * 64];
                float acc = 0.f;
#pragma unroll
                for (int d4 = 0; d4 < 16; d4++) {
                    float4 kv = kr[d4];
                    acc += q[d4 * 4 + 0] * kv.x + q[d4 * 4 + 1] * kv.y +
                           q[d4 * 4 + 2] * kv.z + q[d4 * 4 + 3] * kv.w;
                }
                s[j] = acc;
                tmax = fmaxf(tmax, acc);
            }
            float mn = fmaxf(m, tmax);
            float corr = __expf(m - mn);
            l *= corr;
#pragma unroll
            for (int d = 0; d < 64; d++) o[d] *= corr;
#pragma unroll
            for (int j = 0; j < 16; j++) {
                float p = __expf(s[j] - mn);
                l += p;
                const float4* vr = (const float4*)&Vs[(jc + j) * 64];
#pragma unroll
                for (int d4 = 0; d4 < 16; d4++) {
                    float4 vv = vr[d4];
                    o[d4 * 4 + 0] += p * vv.x;
                    o[d4 * 4 + 1] += p * vv.y;
                    o[d4 * 4 + 2] += p * vv.z;
                    o[d4 * 4 + 3] += p * vv.w;
                }
            }
            m = mn;
        }
    }
    float inv = 1.f / l;
    float4* op = (float4*)&g_ao[((size_t)b * HW + n) * D];
#pragma unroll
    for (int i = 0; i < 16; i++) {
        float4 t;
        t.x = o[4 * i + 0] * inv;
        t.y = o[4 * i + 1] * inv;
        t.z = o[4 * i + 2] * inv;
        t.w = o[4 * i + 3] * inv;
        op[i] = t;
    }
}

// ---------------------------------------------------------------------------
// 4. Output projection + residual:
//    out[b][c][n] = bo[c] + x[b][c][n] + sum_d wo[c][d] * ao[b][n][d]
//    Tile: 32 c x 64 n per block, K=D=64 fully resident in smem.
// ---------------------------------------------------------------------------
__global__ void outproj_kernel(const float* __restrict__ x,
                               const float* __restrict__ wo,
                               const float* __restrict__ bo,
                               float* __restrict__ out) {
    __shared__ float ws[32][64];  // [c][d]
    __shared__ float os[64][68];  // [n][d], pad 68 -> conflict-free LDS.128 phases
    int b = blockIdx.z;
    int c0 = blockIdx.y * 32;
    int n0 = blockIdx.x * 64;
    int tid = threadIdx.x;

#pragma unroll
    for (int i = 0; i < 2; i++) {
        int id = (tid + i * 256) * 4;
        int c = id >> 6, d = id & 63;
        *(float4*)&ws[c][d] = *(const float4*)&wo[(c0 + c) * D + d];
    }
    const float* ab = g_ao + ((size_t)b * HW + n0) * D;
#pragma unroll
    for (int i = 0; i < 4; i++) {
        int id = (tid + i * 256) * 4;
        int nn = id >> 6, d = id & 63;
        *(float4*)&os[nn][d] = *(const float4*)&ab[nn * 64 + d];
    }
    __syncthreads();

#pragma unroll
    for (int i = 0; i < 8; i++) {
        int idx = tid + i * 256;
        int cl = idx >> 6, nl = idx & 63;
        const float4* wr = (const float4*)&ws[cl][0];
        const float4* orow = (const float4*)&os[nl][0];
        float acc = 0.f;
#pragma unroll
        for (int d4 = 0; d4 < 16; d4++) {
            float4 a = wr[d4];
            float4 bv = orow[d4];
            acc += a.x * bv.x + a.y * bv.y + a.z * bv.z + a.w * bv.w;
        }
        size_t gi = ((size_t)b * C + c0 + cl) * HW + n0 + nl;
        out[gi] = acc + bo[c0 + cl] + x[gi];
    }
}

// ---------------------------------------------------------------------------
extern "C" void kernel_launch(void* const* d_in, const int* in_sizes, int n_in,
                              void* d_out, int out_size) {
    const float* x     = (const float*)d_in[0];
    const float* gamma = (const float*)d_in[1];
    const float* beta  = (const float*)d_in[2];
    const float* wq    = (const float*)d_in[3];
    const float* bq    = (const float*)d_in[4];
    const float* wk    = (const float*)d_in[5];
    const float* bk    = (const float*)d_in[6];
    const float* wv    = (const float*)d_in[7];
    const float* bv    = (const float*)d_in[8];
    const float* wo    = (const float*)d_in[9];
    const float* bo    = (const float*)d_in[10];
    float* out = (float*)d_out;

    gn_kernel<<<BB * GROUPS, 512>>>(x, gamma, beta);

    dim3 pg(HW / 64, BB);
    proj_kernel<<<pg, 256>>>(wq, bq, 0);
    proj_kernel<<<pg, 256>>>(wk, bk, 1);
    proj_kernel<<<pg, 256>>>(wv, bv, 2);

    attn_kernel<<<dim3(HW / 64, BB), 64>>>();

    outproj_kernel<<<dim3(HW / 64, C / 32, BB), 256>>>(x, wo, bo, out);
}

// round 3
// speedup vs baseline: 5.9374x; 5.9374x over previous
#include <cuda_runtime.h>
#include <cuda_fp16.h>
#include <cstdint>

#define BB 4
#define C 512
#define D 64
#define HW 4096
#define GROUPS 32
#define CPG 16
#define EPS 1e-5f

// Scratch (device globals — no allocation allowed)
__device__ float g_xn[BB * C * HW];     // normalized x, [B,C,N]
__device__ __half g_qh[BB * HW * D];    // [B,N,D] fp16, pre-scaled by D^-0.5
__device__ __half g_kh[BB * HW * D];    // [B,N,D] fp16
__device__ __half g_vth[BB * D * HW];   // [B,D,N] fp16 (V transposed)
__device__ float g_ao[BB * HW * D];     // attention output [B,N,D] fp32

// ---------------------------------------------------------------------------
// helpers
// ---------------------------------------------------------------------------
__device__ __forceinline__ uint32_t smem_u32(const void* p) {
    uint32_t a;
    asm("{ .reg .u64 t; cvta.to.shared.u64 t, %1; cvt.u32.u64 %0, t; }" : "=r"(a) : "l"(p));
    return a;
}
__device__ __forceinline__ void cp16(uint32_t s, const void* g) {
    asm volatile("cp.async.cg.shared.global [%0], [%1], 16;" :: "r"(s), "l"(g));
}
__device__ __forceinline__ void cp_commit() { asm volatile("cp.async.commit_group;"); }
__device__ __forceinline__ void cp_wait0() { asm volatile("cp.async.wait_group 0;" ::: "memory"); }

__device__ __forceinline__ void mma_f16(float& d0, float& d1, float& d2, float& d3,
                                        uint32_t a0, uint32_t a1, uint32_t a2, uint32_t a3,
                                        uint32_t b0, uint32_t b1,
                                        float c0, float c1, float c2, float c3) {
    asm volatile(
        "mma.sync.aligned.m16n8k16.row.col.f32.f16.f16.f32 "
        "{%0,%1,%2,%3},{%4,%5,%6,%7},{%8,%9},{%10,%11,%12,%13};"
        : "=f"(d0), "=f"(d1), "=f"(d2), "=f"(d3)
        : "r"(a0), "r"(a1), "r"(a2), "r"(a3), "r"(b0), "r"(b1),
          "f"(c0), "f"(c1), "f"(c2), "f"(c3));
}

__device__ __forceinline__ uint32_t packh2(float lo, float hi) {
    __half2 h = __floats2half2_rn(lo, hi);
    return *(uint32_t*)&h;
}

// ---------------------------------------------------------------------------
// 1. GroupNorm
// ---------------------------------------------------------------------------
__global__ void gn_kernel(const float* __restrict__ x,
                          const float* __restrict__ gamma,
                          const float* __restrict__ beta) {
    int bg = blockIdx.x;
    int b = bg / GROUPS, g = bg % GROUPS;
    const float* xp = x + ((size_t)b * C + g * CPG) * HW;
    float* op = g_xn + ((size_t)b * C + g * CPG) * HW;
    const int NE = CPG * HW;

    float s = 0.f, ss = 0.f;
    for (int i = threadIdx.x * 4; i < NE; i += blockDim.x * 4) {
        float4 v = *(const float4*)(xp + i);
        s += v.x + v.y + v.z + v.w;
        ss += v.x * v.x + v.y * v.y + v.z * v.z + v.w * v.w;
    }
    __shared__ float sbuf[32], ssbuf[32];
#pragma unroll
    for (int o = 16; o; o >>= 1) {
        s += __shfl_xor_sync(~0u, s, o);
        ss += __shfl_xor_sync(~0u, ss, o);
    }
    int w = threadIdx.x >> 5;
    if ((threadIdx.x & 31) == 0) { sbuf[w] = s; ssbuf[w] = ss; }
    __syncthreads();
    int nw = blockDim.x >> 5;
    if (threadIdx.x < 32) {
        s = threadIdx.x < nw ? sbuf[threadIdx.x] : 0.f;
        ss = threadIdx.x < nw ? ssbuf[threadIdx.x] : 0.f;
#pragma unroll
        for (int o = 16; o; o >>= 1) {
            s += __shfl_xor_sync(~0u, s, o);
            ss += __shfl_xor_sync(~0u, ss, o);
        }
        if (threadIdx.x == 0) { sbuf[0] = s; ssbuf[0] = ss; }
    }
    __syncthreads();
    float mean = sbuf[0] / NE;
    float var = ssbuf[0] / NE - mean * mean;
    float rstd = rsqrtf(var + EPS);

    for (int i = threadIdx.x * 4; i < NE; i += blockDim.x * 4) {
        int c = g * CPG + (i >> 12);
        float ga = gamma[c] * rstd;
        float be = beta[c] - mean * ga;
        float4 v = *(const float4*)(xp + i);
        v.x = v.x * ga + be;
        v.y = v.y * ga + be;
        v.z = v.z * ga + be;
        v.w = v.w * ga + be;
        *(float4*)(op + i) = v;
    }
}

// ---------------------------------------------------------------------------
// 2. Fused QKV projection (z = which). fp16 outputs; q pre-scaled 0.125;
//    v written transposed [B,D,N].
// ---------------------------------------------------------------------------
__global__ void proj_kernel(const float* __restrict__ wq, const float* __restrict__ bq,
                            const float* __restrict__ wk, const float* __restrict__ bk,
                            const float* __restrict__ wv, const float* __restrict__ bv) {
    __shared__ float xs[32][68];
    __shared__ float ws[64][33];
    int which = blockIdx.z;
    int b = blockIdx.y;
    int n0 = blockIdx.x * 64;
    int tid = threadIdx.x;
    int tx = tid & 15, ty = tid >> 4;
    const float* w = (which == 0) ? wq : (which == 1) ? wk : wv;
    const float* bias = (which == 0) ? bq : (which == 1) ? bk : bv;

    float acc[4][4] = {};
    const float* xb = g_xn + (size_t)b * C * HW;

    for (int k0 = 0; k0 < C; k0 += 32) {
#pragma unroll
        for (int i = 0; i < 2; i++) {
            int idx = (tid + i * 256) * 4;
            int kk = idx >> 6, nn = idx & 63;
            *(float4*)&xs[kk][nn] = *(const float4*)&xb[(size_t)(k0 + kk) * HW + n0 + nn];
        }
#pragma unroll
        for (int i = 0; i < 2; i++) {
            int idx = (tid + i * 256) * 4;
            int d = idx >> 5, kk = idx & 31;
            float4 t = *(const float4*)&w[d * C + k0 + kk];
            ws[d][kk] = t.x; ws[d][kk + 1] = t.y; ws[d][kk + 2] = t.z; ws[d][kk + 3] = t.w;
        }
        __syncthreads();
#pragma unroll
        for (int kk = 0; kk < 32; kk++) {
            float4 a4 = *(const float4*)&xs[kk][tx * 4];
            float a[4] = {a4.x, a4.y, a4.z, a4.w};
            float bb[4];
#pragma unroll
            for (int i = 0; i < 4; i++) bb[i] = ws[ty * 4 + i][kk];
#pragma unroll
            for (int i = 0; i < 4; i++)
#pragma unroll
                for (int j = 0; j < 4; j++) acc[i][j] += bb[i] * a[j];
        }
        __syncthreads();
    }
#pragma unroll
    for (int i = 0; i < 4; i++) {
        float bi = bias[ty * 4 + i];
        int d = ty * 4 + i;
#pragma unroll
        for (int j = 0; j < 4; j++) {
            int n = n0 + tx * 4 + j;
            float val = acc[i][j] + bi;
            if (which == 0) {
                g_qh[((size_t)b * HW + n) * D + d] = __float2half(val * 0.125f);
            } else if (which == 1) {
                g_kh[((size_t)b * HW + n) * D + d] = __float2half(val);
            } else {
                g_vth[((size_t)b * D + d) * HW + n] = __float2half(val);
            }
        }
    }
}

// ---------------------------------------------------------------------------
// 3. fp16 mma.sync flash attention.
//    CTA: 256 threads / 8 warps / 128 queries. 32 k-tiles of 128 keys.
//    No max-subtraction (scores bounded ~|7|).
//    SMEM: Qh [128 x 144B], Kh dbl [128 x 144B], Vth dbl [64 x 272B]
// ---------------------------------------------------------------------------
#define QPITCH 144
#define KPITCH 144
#define VPITCH 272
#define SQ_OFF 0
#define SK_OFF 18432
#define KBYTES 18432
#define SV_OFF (18432 + 2 * 18432)
#define VBYTES 17408
#define ATTN_SMEM (SV_OFF + 2 * VBYTES)   // 90112

__global__ void __launch_bounds__(256, 1) attn_kernel() {
    extern __shared__ char smem[];
    const uint32_t sb = smem_u32(smem);
    const int tid = threadIdx.x, wid = tid >> 5, lane = tid & 31;
    const int g = lane >> 2, t = lane & 3;
    const int b = blockIdx.y;
    const int n0 = blockIdx.x * 128;

    const __half* qh = g_qh + ((size_t)b * HW + n0) * D;
    const __half* kh = g_kh + (size_t)b * HW * D;
    const __half* vh = g_vth + (size_t)b * D * HW;

    // Prologue: Q tile + K/V tile 0 (buf 0)
    for (int i = tid; i < 1024; i += 256) {
        int r = i >> 3, ch = i & 7;
        cp16(sb + SQ_OFF + r * QPITCH + ch * 16, qh + r * 64 + ch * 8);
    }
    for (int i = tid; i < 1024; i += 256) {
        int r = i >> 3, ch = i & 7;
        cp16(sb + SK_OFF + r * KPITCH + ch * 16, kh + (size_t)r * 64 + ch * 8);
    }
    for (int i = tid; i < 1024; i += 256) {
        int r = i >> 4, ch = i & 15;
        cp16(sb + SV_OFF + r * VPITCH + ch * 16, vh + (size_t)r * HW + ch * 8);
    }
    cp_commit();
    cp_wait0();
    __syncthreads();

    // Load Q fragments (persistent): 4 k-steps x 4 regs
    uint32_t qa[4][4];
    {
        const char* qbase = smem + SQ_OFF + (wid * 16 + g) * QPITCH + t * 4;
#pragma unroll
        for (int s = 0; s < 4; s++) {
            qa[s][0] = *(const uint32_t*)(qbase + s * 32);
            qa[s][1] = *(const uint32_t*)(qbase + 8 * QPITCH + s * 32);
            qa[s][2] = *(const uint32_t*)(qbase + s * 32 + 16);
            qa[s][3] = *(const uint32_t*)(qbase + 8 * QPITCH + s * 32 + 16);
        }
    }

    float o[8][4];
#pragma unroll
    for (int j = 0; j < 8; j++)
#pragma unroll
        for (int k = 0; k < 4; k++) o[j][k] = 0.f;
    float l0 = 0.f, l1 = 0.f;

    for (int it = 0; it < 32; it++) {
        int buf = it & 1;

        // prefetch next tile into other buffer
        if (it + 1 < 32) {
            int t1 = (it + 1) * 128;
            int nb = buf ^ 1;
            for (int i = tid; i < 1024; i += 256) {
                int r = i >> 3, ch = i & 7;
                cp16(sb + SK_OFF + nb * KBYTES + r * KPITCH + ch * 16,
                     kh + (size_t)(t1 + r) * 64 + ch * 8);
            }
            for (int i = tid; i < 1024; i += 256) {
                int r = i >> 4, ch = i & 15;
                cp16(sb + SV_OFF + nb * VBYTES + r * VPITCH + ch * 16,
                     vh + (size_t)r * HW + t1 + ch * 8);
            }
        }
        cp_commit();

        const char* kbase = smem + SK_OFF + buf * KBYTES + g * KPITCH + t * 4;
        const char* vbase = smem + SV_OFF + buf * VBYTES + g * VPITCH + t * 4;

        // S = Q.K^T, exp, pack to P A-frags
        uint32_t pa[8][4];
#pragma unroll
        for (int j = 0; j < 16; j++) {
            float c0 = 0.f, c1 = 0.f, c2 = 0.f, c3 = 0.f;
            const char* krow = kbase + 8 * j * KPITCH;
#pragma unroll
            for (int s = 0; s < 4; s++) {
                uint32_t b0 = *(const uint32_t*)(krow + s * 32);
                uint32_t b1 = *(const uint32_t*)(krow + s * 32 + 16);
                mma_f16(c0, c1, c2, c3, qa[s][0], qa[s][1], qa[s][2], qa[s][3],
                        b0, b1, c0, c1, c2, c3);
            }
            float p0 = __expf(c0), p1 = __expf(c1);
            float p2 = __expf(c2), p3 = __expf(c3);
            l0 += p0 + p1;
            l1 += p2 + p3;
            uint32_t lo = packh2(p0, p1), hi = packh2(p2, p3);
            pa[j >> 1][(j & 1) * 2 + 0] = lo;
            pa[j >> 1][(j & 1) * 2 + 1] = hi;
        }

        // O += P.V
#pragma unroll
        for (int j = 0; j < 8; j++) {
            const char* vrow = vbase + 8 * j * VPITCH;
#pragma unroll
            for (int s = 0; s < 8; s++) {
                uint32_t b0 = *(const uint32_t*)(vrow + s * 32);
                uint32_t b1 = *(const uint32_t*)(vrow + s * 32 + 16);
                mma_f16(o[j][0], o[j][1], o[j][2], o[j][3],
                        pa[s][0], pa[s][1], pa[s][2], pa[s][3],
                        b0, b1, o[j][0], o[j][1], o[j][2], o[j][3]);
            }
        }

        if (it + 1 < 32) {
            cp_wait0();
            __syncthreads();
        }
    }

    // reduce l across the 4 lanes sharing a row
    l0 += __shfl_xor_sync(~0u, l0, 1);
    l0 += __shfl_xor_sync(~0u, l0, 2);
    l1 += __shfl_xor_sync(~0u, l1, 1);
    l1 += __shfl_xor_sync(~0u, l1, 2);
    float i0 = 1.f / l0, i1 = 1.f / l1;

    float* ao = g_ao + ((size_t)b * HW + n0 + wid * 16) * D;
#pragma unroll
    for (int j = 0; j < 8; j++) {
        float2 r0 = {o[j][0] * i0, o[j][1] * i0};
        float2 r1 = {o[j][2] * i1, o[j][3] * i1};
        *(float2*)(ao + (size_t)g * 64 + 8 * j + 2 * t) = r0;
        *(float2*)(ao + (size_t)(g + 8) * 64 + 8 * j + 2 * t) = r1;
    }
}

// ---------------------------------------------------------------------------
// 4. Output projection + residual
// ---------------------------------------------------------------------------
__global__ void outproj_kernel(const float* __restrict__ x,
                               const float* __restrict__ wo,
                               const float* __restrict__ bo,
                               float* __restrict__ out) {
    __shared__ float ws[32][64];
    __shared__ float os[64][68];
    int b = blockIdx.z;
    int c0 = blockIdx.y * 32;
    int n0 = blockIdx.x * 64;
    int tid = threadIdx.x;

#pragma unroll
    for (int i = 0; i < 2; i++) {
        int id = (tid + i * 256) * 4;
        int c = id >> 6, d = id & 63;
        *(float4*)&ws[c][d] = *(const float4*)&wo[(c0 + c) * D + d];
    }
    const float* ab = g_ao + ((size_t)b * HW + n0) * D;
#pragma unroll
    for (int i = 0; i < 4; i++) {
        int id = (tid + i * 256) * 4;
        int nn = id >> 6, d = id & 63;
        *(float4*)&os[nn][d] = *(const float4*)&ab[nn * 64 + d];
    }
    __syncthreads();

#pragma unroll
    for (int i = 0; i < 8; i++) {
        int idx = tid + i * 256;
        int cl = idx >> 6, nl = idx & 63;
        const float4* wr = (const float4*)&ws[cl][0];
        const float4* orow = (const float4*)&os[nl][0];
        float acc = 0.f;
#pragma unroll
        for (int d4 = 0; d4 < 16; d4++) {
            float4 a = wr[d4];
            float4 bv = orow[d4];
            acc += a.x * bv.x + a.y * bv.y + a.z * bv.z + a.w * bv.w;
        }
        size_t gi = ((size_t)b * C + c0 + cl) * HW + n0 + nl;
        out[gi] = acc + bo[c0 + cl] + x[gi];
    }
}

// ---------------------------------------------------------------------------
extern "C" void kernel_launch(void* const* d_in, const int* in_sizes, int n_in,
                              void* d_out, int out_size) {
    const float* x     = (const float*)d_in[0];
    const float* gamma = (const float*)d_in[1];
    const float* beta  = (const float*)d_in[2];
    const float* wq    = (const float*)d_in[3];
    const float* bq    = (const float*)d_in[4];
    const float* wk    = (const float*)d_in[5];
    const float* bk    = (const float*)d_in[6];
    const float* wv    = (const float*)d_in[7];
    const float* bv    = (const float*)d_in[8];
    const float* wo    = (const float*)d_in[9];
    const float* bo    = (const float*)d_in[10];
    float* out = (float*)d_out;

    static int attr_done = 0;
    if (!attr_done) {
        cudaFuncSetAttribute(attn_kernel, cudaFuncAttributeMaxDynamicSharedMemorySize,
                             ATTN_SMEM);
        attr_done = 1;
    }

    gn_kernel<<<BB * GROUPS, 512>>>(x, gamma, beta);

    proj_kernel<<<dim3(HW / 64, BB, 3), 256>>>(wq, bq, wk, bk, wv, bv);

    attn_kernel<<<dim3(HW / 128, BB), 256, ATTN_SMEM>>>();

    outproj_kernel<<<dim3(HW / 64, C / 32, BB), 256>>>(x, wo, bo, out);
}

// round 4
// speedup vs baseline: 6.4221x; 1.0816x over previous
#include <cuda_runtime.h>
#include <cuda_fp16.h>
#include <cstdint>

#define BB 4
#define C 512
#define D 64
#define HW 4096
#define GROUPS 32
#define CPG 16
#define EPS 1e-5f

// Scratch (device globals — no allocation allowed)
__device__ float g_scale[BB * C];       // per-channel gamma*rstd
__device__ float g_bias[BB * C];        // per-channel beta - mean*scale
__device__ __half g_qh[BB * HW * D];    // [B,N,D] fp16, pre-scaled by D^-0.5
__device__ __half g_kh[BB * HW * D];    // [B,N,D] fp16
__device__ __half g_vth[BB * D * HW];   // [B,D,N] fp16 (V transposed)
__device__ float g_ao[BB * HW * D];     // attention output [B,N,D] fp32

// ---------------------------------------------------------------------------
// helpers
// ---------------------------------------------------------------------------
__device__ __forceinline__ uint32_t smem_u32(const void* p) {
    uint32_t a;
    asm("{ .reg .u64 t; cvta.to.shared.u64 t, %1; cvt.u32.u64 %0, t; }" : "=r"(a) : "l"(p));
    return a;
}
__device__ __forceinline__ void cp16(uint32_t s, const void* g) {
    asm volatile("cp.async.cg.shared.global [%0], [%1], 16;" :: "r"(s), "l"(g));
}
__device__ __forceinline__ void cp_commit() { asm volatile("cp.async.commit_group;"); }
__device__ __forceinline__ void cp_wait0() { asm volatile("cp.async.wait_group 0;" ::: "memory"); }

__device__ __forceinline__ void mma_f16(float& d0, float& d1, float& d2, float& d3,
                                        uint32_t a0, uint32_t a1, uint32_t a2, uint32_t a3,
                                        uint32_t b0, uint32_t b1,
                                        float c0, float c1, float c2, float c3) {
    asm volatile(
        "mma.sync.aligned.m16n8k16.row.col.f32.f16.f16.f32 "
        "{%0,%1,%2,%3},{%4,%5,%6,%7},{%8,%9},{%10,%11,%12,%13};"
        : "=f"(d0), "=f"(d1), "=f"(d2), "=f"(d3)
        : "r"(a0), "r"(a1), "r"(a2), "r"(a3), "r"(b0), "r"(b1),
          "f"(c0), "f"(c1), "f"(c2), "f"(c3));
}

__device__ __forceinline__ uint32_t packh2(float lo, float hi) {
    __half2 h = __floats2half2_rn(lo, hi);
    return *(uint32_t*)&h;
}

// ---------------------------------------------------------------------------
// 1. GroupNorm stats: one block per (b, group); writes per-channel scale/bias.
// ---------------------------------------------------------------------------
__global__ void gn_stats_kernel(const float* __restrict__ x,
                                const float* __restrict__ gamma,
                                const float* __restrict__ beta) {
    int bg = blockIdx.x;
    int b = bg / GROUPS, g = bg % GROUPS;
    const float* xp = x + ((size_t)b * C + g * CPG) * HW;
    const int NE = CPG * HW;

    float s = 0.f, ss = 0.f;
    for (int i = threadIdx.x * 4; i < NE; i += blockDim.x * 4) {
        float4 v = *(const float4*)(xp + i);
        s += v.x + v.y + v.z + v.w;
        ss += v.x * v.x + v.y * v.y + v.z * v.z + v.w * v.w;
    }
    __shared__ float sbuf[32], ssbuf[32];
#pragma unroll
    for (int o = 16; o; o >>= 1) {
        s += __shfl_xor_sync(~0u, s, o);
        ss += __shfl_xor_sync(~0u, ss, o);
    }
    int w = threadIdx.x >> 5;
    if ((threadIdx.x & 31) == 0) { sbuf[w] = s; ssbuf[w] = ss; }
    __syncthreads();
    int nw = blockDim.x >> 5;
    if (threadIdx.x < 32) {
        s = threadIdx.x < nw ? sbuf[threadIdx.x] : 0.f;
        ss = threadIdx.x < nw ? ssbuf[threadIdx.x] : 0.f;
#pragma unroll
        for (int o = 16; o; o >>= 1) {
            s += __shfl_xor_sync(~0u, s, o);
            ss += __shfl_xor_sync(~0u, ss, o);
        }
        if (threadIdx.x == 0) { sbuf[0] = s; ssbuf[0] = ss; }
    }
    __syncthreads();
    float mean = sbuf[0] / NE;
    float var = ssbuf[0] / NE - mean * mean;
    float rstd = rsqrtf(var + EPS);

    if (threadIdx.x < CPG) {
        int c = g * CPG + threadIdx.x;
        float ga = gamma[c] * rstd;
        g_scale[b * C + c] = ga;
        g_bias[b * C + c] = beta[c] - mean * ga;
    }
}

// ---------------------------------------------------------------------------
// 2. Fused GN-normalize + QKV projection (z = which). fp16 outputs;
//    q pre-scaled 0.125; v written transposed [B,D,N].
//    Inner loop: 8 LDS.128 per 64 FFMA.
// ---------------------------------------------------------------------------
__global__ void __launch_bounds__(256) proj_kernel(
        const float* __restrict__ x,
        const float* __restrict__ wq, const float* __restrict__ bq,
        const float* __restrict__ wk, const float* __restrict__ bk,
        const float* __restrict__ wv, const float* __restrict__ bv) {
    __shared__ float xs[32][68];   // [kk][n]  (normalized)
    __shared__ float ws[64][36];   // [d][kk]  kk float4-aligned
    __shared__ float sga[C], sbe[C];
    int which = blockIdx.z;
    int b = blockIdx.y;
    int n0 = blockIdx.x * 64;
    int tid = threadIdx.x;
    int tx = tid & 15, ty = tid >> 4;
    const float* w = (which == 0) ? wq : (which == 1) ? wk : wv;
    const float* bias = (which == 0) ? bq : (which == 1) ? bk : bv;

    // preload per-channel scale/bias
#pragma unroll
    for (int i = 0; i < C / 4; i += 256) {
        int id = (tid + i);
        if (id < C / 4) {
            *(float4*)&sga[id * 4] = *(const float4*)&g_scale[b * C + id * 4];
            *(float4*)&sbe[id * 4] = *(const float4*)&g_bias[b * C + id * 4];
        }
    }
    __syncthreads();

    float acc[4][4] = {};
    const float* xb = x + (size_t)b * C * HW;

    for (int k0 = 0; k0 < C; k0 += 32) {
#pragma unroll
        for (int i = 0; i < 2; i++) {
            int idx = (tid + i * 256) * 4;
            int kk = idx >> 6, nn = idx & 63;
            float ga = sga[k0 + kk], be = sbe[k0 + kk];
            float4 v = *(const float4*)&xb[(size_t)(k0 + kk) * HW + n0 + nn];
            v.x = v.x * ga + be;
            v.y = v.y * ga + be;
            v.z = v.z * ga + be;
            v.w = v.w * ga + be;
            *(float4*)&xs[kk][nn] = v;
        }
#pragma unroll
        for (int i = 0; i < 2; i++) {
            int idx = (tid + i * 256) * 4;
            int d = idx >> 5, kk = idx & 31;
            *(float4*)&ws[d][kk] = *(const float4*)&w[d * C + k0 + kk];
        }
        __syncthreads();
#pragma unroll
        for (int k4 = 0; k4 < 8; k4++) {
            float4 wf[4], xf[4];
#pragma unroll
            for (int i = 0; i < 4; i++) wf[i] = *(const float4*)&ws[ty * 4 + i][k4 * 4];
#pragma unroll
            for (int m = 0; m < 4; m++) xf[m] = *(const float4*)&xs[k4 * 4 + m][tx * 4];
#pragma unroll
            for (int i = 0; i < 4; i++) {
                acc[i][0] += wf[i].x * xf[0].x + wf[i].y * xf[1].x + wf[i].z * xf[2].x + wf[i].w * xf[3].x;
                acc[i][1] += wf[i].x * xf[0].y + wf[i].y * xf[1].y + wf[i].z * xf[2].y + wf[i].w * xf[3].y;
                acc[i][2] += wf[i].x * xf[0].z + wf[i].y * xf[1].z + wf[i].z * xf[2].z + wf[i].w * xf[3].z;
                acc[i][3] += wf[i].x * xf[0].w + wf[i].y * xf[1].w + wf[i].z * xf[2].w + wf[i].w * xf[3].w;
            }
        }
        __syncthreads();
    }
#pragma unroll
    for (int i = 0; i < 4; i++) {
        float bi = bias[ty * 4 + i];
        int d = ty * 4 + i;
#pragma unroll
        for (int j = 0; j < 4; j++) {
            int n = n0 + tx * 4 + j;
            float val = acc[i][j] + bi;
            if (which == 0) {
                g_qh[((size_t)b * HW + n) * D + d] = __float2half(val * 0.125f);
            } else if (which == 1) {
                g_kh[((size_t)b * HW + n) * D + d] = __float2half(val);
            } else {
                g_vth[((size_t)b * D + d) * HW + n] = __float2half(val);
            }
        }
    }
}

// ---------------------------------------------------------------------------
// 3. fp16 mma.sync flash attention (unchanged from R3).
// ---------------------------------------------------------------------------
#define QPITCH 144
#define KPITCH 144
#define VPITCH 272
#define SQ_OFF 0
#define SK_OFF 18432
#define KBYTES 18432
#define SV_OFF (18432 + 2 * 18432)
#define VBYTES 17408
#define ATTN_SMEM (SV_OFF + 2 * VBYTES)   // 90112

__global__ void __launch_bounds__(256, 1) attn_kernel() {
    extern __shared__ char smem[];
    const uint32_t sb = smem_u32(smem);
    const int tid = threadIdx.x, wid = tid >> 5, lane = tid & 31;
    const int g = lane >> 2, t = lane & 3;
    const int b = blockIdx.y;
    const int n0 = blockIdx.x * 128;

    const __half* qh = g_qh + ((size_t)b * HW + n0) * D;
    const __half* kh = g_kh + (size_t)b * HW * D;
    const __half* vh = g_vth + (size_t)b * D * HW;

    for (int i = tid; i < 1024; i += 256) {
        int r = i >> 3, ch = i & 7;
        cp16(sb + SQ_OFF + r * QPITCH + ch * 16, qh + r * 64 + ch * 8);
    }
    for (int i = tid; i < 1024; i += 256) {
        int r = i >> 3, ch = i & 7;
        cp16(sb + SK_OFF + r * KPITCH + ch * 16, kh + (size_t)r * 64 + ch * 8);
    }
    for (int i = tid; i < 1024; i += 256) {
        int r = i >> 4, ch = i & 15;
        cp16(sb + SV_OFF + r * VPITCH + ch * 16, vh + (size_t)r * HW + ch * 8);
    }
    cp_commit();
    cp_wait0();
    __syncthreads();

    uint32_t qa[4][4];
    {
        const char* qbase = smem + SQ_OFF + (wid * 16 + g) * QPITCH + t * 4;
#pragma unroll
        for (int s = 0; s < 4; s++) {
            qa[s][0] = *(const uint32_t*)(qbase + s * 32);
            qa[s][1] = *(const uint32_t*)(qbase + 8 * QPITCH + s * 32);
            qa[s][2] = *(const uint32_t*)(qbase + s * 32 + 16);
            qa[s][3] = *(const uint32_t*)(qbase + 8 * QPITCH + s * 32 + 16);
        }
    }

    float o[8][4];
#pragma unroll
    for (int j = 0; j < 8; j++)
#pragma unroll
        for (int k = 0; k < 4; k++) o[j][k] = 0.f;
    float l0 = 0.f, l1 = 0.f;

    for (int it = 0; it < 32; it++) {
        int buf = it & 1;

        if (it + 1 < 32) {
            int t1 = (it + 1) * 128;
            int nb = buf ^ 1;
            for (int i = tid; i < 1024; i += 256) {
                int r = i >> 3, ch = i & 7;
                cp16(sb + SK_OFF + nb * KBYTES + r * KPITCH + ch * 16,
                     kh + (size_t)(t1 + r) * 64 + ch * 8);
            }
            for (int i = tid; i < 1024; i += 256) {
                int r = i >> 4, ch = i & 15;
                cp16(sb + SV_OFF + nb * VBYTES + r * VPITCH + ch * 16,
                     vh + (size_t)r * HW + t1 + ch * 8);
            }
        }
        cp_commit();

        const char* kbase = smem + SK_OFF + buf * KBYTES + g * KPITCH + t * 4;
        const char* vbase = smem + SV_OFF + buf * VBYTES + g * VPITCH + t * 4;

        uint32_t pa[8][4];
#pragma unroll
        for (int j = 0; j < 16; j++) {
            float c0 = 0.f, c1 = 0.f, c2 = 0.f, c3 = 0.f;
            const char* krow = kbase + 8 * j * KPITCH;
#pragma unroll
            for (int s = 0; s < 4; s++) {
                uint32_t b0 = *(const uint32_t*)(krow + s * 32);
                uint32_t b1 = *(const uint32_t*)(krow + s * 32 + 16);
                mma_f16(c0, c1, c2, c3, qa[s][0], qa[s][1], qa[s][2], qa[s][3],
                        b0, b1, c0, c1, c2, c3);
            }
            float p0 = __expf(c0), p1 = __expf(c1);
            float p2 = __expf(c2), p3 = __expf(c3);
            l0 += p0 + p1;
            l1 += p2 + p3;
            uint32_t lo = packh2(p0, p1), hi = packh2(p2, p3);
            pa[j >> 1][(j & 1) * 2 + 0] = lo;
            pa[j >> 1][(j & 1) * 2 + 1] = hi;
        }

#pragma unroll
        for (int j = 0; j < 8; j++) {
            const char* vrow = vbase + 8 * j * VPITCH;
#pragma unroll
            for (int s = 0; s < 8; s++) {
                uint32_t b0 = *(const uint32_t*)(vrow + s * 32);
                uint32_t b1 = *(const uint32_t*)(vrow + s * 32 + 16);
                mma_f16(o[j][0], o[j][1], o[j][2], o[j][3],
                        pa[s][0], pa[s][1], pa[s][2], pa[s][3],
                        b0, b1, o[j][0], o[j][1], o[j][2], o[j][3]);
            }
        }

        if (it + 1 < 32) {
            cp_wait0();
            __syncthreads();
        }
    }

    l0 += __shfl_xor_sync(~0u, l0, 1);
    l0 += __shfl_xor_sync(~0u, l0, 2);
    l1 += __shfl_xor_sync(~0u, l1, 1);
    l1 += __shfl_xor_sync(~0u, l1, 2);
    float i0 = 1.f / l0, i1 = 1.f / l1;

    float* ao = g_ao + ((size_t)b * HW + n0 + wid * 16) * D;
#pragma unroll
    for (int j = 0; j < 8; j++) {
        float2 r0 = {o[j][0] * i0, o[j][1] * i0};
        float2 r1 = {o[j][2] * i1, o[j][3] * i1};
        *(float2*)(ao + (size_t)g * 64 + 8 * j + 2 * t) = r0;
        *(float2*)(ao + (size_t)(g + 8) * 64 + 8 * j + 2 * t) = r1;
    }
}

// ---------------------------------------------------------------------------
// 4. Output projection + residual. 64c x 64n tile, 256 threads, 4x4/thread.
//    Both operands transposed in smem so inner loop is 8 LDS.128 / 64 FFMA.
// ---------------------------------------------------------------------------
__global__ void __launch_bounds__(256) outproj_kernel(
        const float* __restrict__ x,
        const float* __restrict__ wo,
        const float* __restrict__ bo,
        float* __restrict__ out) {
    __shared__ float wsT[64][68];  // [d][c]
    __shared__ float osT[64][68];  // [d][n]
    int b = blockIdx.z;
    int c0 = blockIdx.y * 64;
    int n0 = blockIdx.x * 64;
    int tid = threadIdx.x;
    int tn = tid & 15, tc = tid >> 4;

    // load + transpose: wo[c][d] -> wsT[d][c], ao[n][d] -> osT[d][n]
#pragma unroll
    for (int i = 0; i < 4; i++) {
        int id = (tid + i * 256) * 4;
        int c = id >> 6, d = id & 63;
        float4 v = *(const float4*)&wo[(size_t)(c0 + c) * D + d];
        wsT[d + 0][c] = v.x;
        wsT[d + 1][c] = v.y;
        wsT[d + 2][c] = v.z;
        wsT[d + 3][c] = v.w;
    }
    const float* ab = g_ao + ((size_t)b * HW + n0) * D;
#pragma unroll
    for (int i = 0; i < 4; i++) {
        int id = (tid + i * 256) * 4;
        int nn = id >> 6, d = id & 63;
        float4 v = *(const float4*)&ab[(size_t)nn * D + d];
        osT[d + 0][nn] = v.x;
        osT[d + 1][nn] = v.y;
        osT[d + 2][nn] = v.z;
        osT[d + 3][nn] = v.w;
    }
    __syncthreads();

    float acc[4][4] = {};
#pragma unroll
    for (int d = 0; d < 64; d++) {
        float4 wf = *(const float4*)&wsT[d][tc * 4];
        float4 of = *(const float4*)&osT[d][tn * 4];
        acc[0][0] += wf.x * of.x; acc[0][1] += wf.x * of.y;
        acc[0][2] += wf.x * of.z; acc[0][3] += wf.x * of.w;
        acc[1][0] += wf.y * of.x; acc[1][1] += wf.y * of.y;
        acc[1][2] += wf.y * of.z; acc[1][3] += wf.y * of.w;
        acc[2][0] += wf.z * of.x; acc[2][1] += wf.z * of.y;
        acc[2][2] += wf.z * of.z; acc[2][3] += wf.z * of.w;
        acc[3][0] += wf.w * of.x; acc[3][1] += wf.w * of.y;
        acc[3][2] += wf.w * of.z; acc[3][3] += wf.w * of.w;
    }

#pragma unroll
    for (int i = 0; i < 4; i++) {
        int c = c0 + tc * 4 + i;
        float bi = bo[c];
        size_t gi = ((size_t)b * C + c) * HW + n0 + tn * 4;
        float4 xr = *(const float4*)&x[gi];
        float4 r;
        r.x = acc[i][0] + bi + xr.x;
        r.y = acc[i][1] + bi + xr.y;
        r.z = acc[i][2] + bi + xr.z;
        r.w = acc[i][3] + bi + xr.w;
        *(float4*)&out[gi] = r;
    }
}

// ---------------------------------------------------------------------------
extern "C" void kernel_launch(void* const* d_in, const int* in_sizes, int n_in,
                              void* d_out, int out_size) {
    const float* x     = (const float*)d_in[0];
    const float* gamma = (const float*)d_in[1];
    const float* beta  = (const float*)d_in[2];
    const float* wq    = (const float*)d_in[3];
    const float* bq    = (const float*)d_in[4];
    const float* wk    = (const float*)d_in[5];
    const float* bk    = (const float*)d_in[6];
    const float* wv    = (const float*)d_in[7];
    const float* bv    = (const float*)d_in[8];
    const float* wo    = (const float*)d_in[9];
    const float* bo    = (const float*)d_in[10];
    float* out = (float*)d_out;

    static int attr_done = 0;
    if (!attr_done) {
        cudaFuncSetAttribute(attn_kernel, cudaFuncAttributeMaxDynamicSharedMemorySize,
                             ATTN_SMEM);
        attr_done = 1;
    }

    gn_stats_kernel<<<BB * GROUPS, 512>>>(x, gamma, beta);

    proj_kernel<<<dim3(HW / 64, BB, 3), 256>>>(x, wq, bq, wk, bk, wv, bv);

    attn_kernel<<<dim3(HW / 128, BB), 256, ATTN_SMEM>>>();

    outproj_kernel<<<dim3(HW / 64, C / 64, BB), 256>>>(x, wo, bo, out);
}

// round 5
// speedup vs baseline: 7.5839x; 1.1809x over previous
#include <cuda_runtime.h>
#include <cuda_fp16.h>
#include <cstdint>

#define BB 4
#define C 512
#define D 64
#define HW 4096
#define GROUPS 32
#define CPG 16
#define EPS 1e-5f

// Scratch (device globals — no allocation allowed)
__device__ float g_scale[BB * C];        // per-channel gamma*rstd
__device__ float g_bias[BB * C];         // per-channel beta - mean*scale
__device__ __half g_xh[BB * HW * C];     // normalized x, transposed [B,N,C] fp16
__device__ __half g_wqh[D * C], g_wkh[D * C], g_wvh[D * C], g_woh[C * D];
__device__ __half g_qh[BB * HW * D];     // [B,N,D] fp16 (q NOT yet scaled; scaled at epilogue)
__device__ __half g_kh[BB * HW * D];     // [B,N,D] fp16
__device__ __half g_vth[BB * D * HW];    // [B,D,N] fp16
__device__ __half g_aoh[BB * HW * D];    // attention output [B,N,D] fp16

// ---------------------------------------------------------------------------
// helpers
// ---------------------------------------------------------------------------
__device__ __forceinline__ uint32_t smem_u32(const void* p) {
    uint32_t a;
    asm("{ .reg .u64 t; cvta.to.shared.u64 t, %1; cvt.u32.u64 %0, t; }" : "=r"(a) : "l"(p));
    return a;
}
__device__ __forceinline__ void cp16(uint32_t s, const void* g) {
    asm volatile("cp.async.cg.shared.global [%0], [%1], 16;" :: "r"(s), "l"(g));
}
__device__ __forceinline__ void cp_commit() { asm volatile("cp.async.commit_group;"); }
__device__ __forceinline__ void cp_wait0() { asm volatile("cp.async.wait_group 0;" ::: "memory"); }

__device__ __forceinline__ void mma_f16(float& d0, float& d1, float& d2, float& d3,
                                        uint32_t a0, uint32_t a1, uint32_t a2, uint32_t a3,
                                        uint32_t b0, uint32_t b1,
                                        float c0, float c1, float c2, float c3) {
    asm volatile(
        "mma.sync.aligned.m16n8k16.row.col.f32.f16.f16.f32 "
        "{%0,%1,%2,%3},{%4,%5,%6,%7},{%8,%9},{%10,%11,%12,%13};"
        : "=f"(d0), "=f"(d1), "=f"(d2), "=f"(d3)
        : "r"(a0), "r"(a1), "r"(a2), "r"(a3), "r"(b0), "r"(b1),
          "f"(c0), "f"(c1), "f"(c2), "f"(c3));
}
__device__ __forceinline__ uint32_t packh2(float lo, float hi) {
    __half2 h = __floats2half2_rn(lo, hi);
    return *(uint32_t*)&h;
}

// ---------------------------------------------------------------------------
// 1. GroupNorm stats: per-channel scale/bias.
// ---------------------------------------------------------------------------
__global__ void gn_stats_kernel(const float* __restrict__ x,
                                const float* __restrict__ gamma,
                                const float* __restrict__ beta) {
    int bg = blockIdx.x;
    int b = bg / GROUPS, g = bg % GROUPS;
    const float* xp = x + ((size_t)b * C + g * CPG) * HW;
    const int NE = CPG * HW;

    float s = 0.f, ss = 0.f;
    for (int i = threadIdx.x * 4; i < NE; i += blockDim.x * 4) {
        float4 v = *(const float4*)(xp + i);
        s += v.x + v.y + v.z + v.w;
        ss += v.x * v.x + v.y * v.y + v.z * v.z + v.w * v.w;
    }
    __shared__ float sbuf[32], ssbuf[32];
#pragma unroll
    for (int o = 16; o; o >>= 1) {
        s += __shfl_xor_sync(~0u, s, o);
        ss += __shfl_xor_sync(~0u, ss, o);
    }
    int w = threadIdx.x >> 5;
    if ((threadIdx.x & 31) == 0) { sbuf[w] = s; ssbuf[w] = ss; }
    __syncthreads();
    int nw = blockDim.x >> 5;
    if (threadIdx.x < 32) {
        s = threadIdx.x < nw ? sbuf[threadIdx.x] : 0.f;
        ss = threadIdx.x < nw ? ssbuf[threadIdx.x] : 0.f;
#pragma unroll
        for (int o = 16; o; o >>= 1) {
            s += __shfl_xor_sync(~0u, s, o);
            ss += __shfl_xor_sync(~0u, ss, o);
        }
        if (threadIdx.x == 0) { sbuf[0] = s; ssbuf[0] = ss; }
    }
    __syncthreads();
    float mean = sbuf[0] / NE;
    float var = ssbuf[0] / NE - mean * mean;
    float rstd = rsqrtf(var + EPS);

    if (threadIdx.x < CPG) {
        int c = g * CPG + threadIdx.x;
        float ga = gamma[c] * rstd;
        g_scale[b * C + c] = ga;
        g_bias[b * C + c] = beta[c] - mean * ga;
    }
}

// ---------------------------------------------------------------------------
// 1b. Weight convert fp32 -> fp16 (all four weights, 32768 elems each)
// ---------------------------------------------------------------------------
__global__ void wcvt_kernel(const float* __restrict__ wq, const float* __restrict__ wk,
                            const float* __restrict__ wv, const float* __restrict__ wo) {
    int id = (blockIdx.x * 256 + threadIdx.x) * 4;
    if (id < D * C) {
        float4 a;
        a = *(const float4*)&wq[id];
        *(__half2*)&g_wqh[id] = __floats2half2_rn(a.x, a.y);
        *(__half2*)&g_wqh[id + 2] = __floats2half2_rn(a.z, a.w);
        a = *(const float4*)&wk[id];
        *(__half2*)&g_wkh[id] = __floats2half2_rn(a.x, a.y);
        *(__half2*)&g_wkh[id + 2] = __floats2half2_rn(a.z, a.w);
        a = *(const float4*)&wv[id];
        *(__half2*)&g_wvh[id] = __floats2half2_rn(a.x, a.y);
        *(__half2*)&g_wvh[id + 2] = __floats2half2_rn(a.z, a.w);
        a = *(const float4*)&wo[id];
        *(__half2*)&g_woh[id] = __floats2half2_rn(a.x, a.y);
        *(__half2*)&g_woh[id + 2] = __floats2half2_rn(a.z, a.w);
    }
}

// ---------------------------------------------------------------------------
// 1c. GN apply + transpose: x[b][c][n] fp32 -> xh[b][n][c] fp16 (64x64 tiles)
// ---------------------------------------------------------------------------
__global__ void __launch_bounds__(256) gn_apply_kernel(const float* __restrict__ x) {
    __shared__ __half sh[64][72];
    __shared__ float sga[64], sbe[64];
    int b = blockIdx.z, c0 = blockIdx.y * 64, n0 = blockIdx.x * 64;
    int tid = threadIdx.x;

    if (tid < 64) {
        sga[tid] = g_scale[b * C + c0 + tid];
        sbe[tid] = g_bias[b * C + c0 + tid];
    }
    __syncthreads();

#pragma unroll
    for (int it = 0; it < 4; it++) {
        int id = (tid + it * 256) * 4;
        int c = id >> 6, n = id & 63;
        float ga = sga[c], be = sbe[c];
        float4 v = *(const float4*)&x[((size_t)b * C + c0 + c) * HW + n0 + n];
        sh[n + 0][c] = __float2half(v.x * ga + be);
        sh[n + 1][c] = __float2half(v.y * ga + be);
        sh[n + 2][c] = __float2half(v.z * ga + be);
        sh[n + 3][c] = __float2half(v.w * ga + be);
    }
    __syncthreads();

#pragma unroll
    for (int it = 0; it < 4; it++) {
        int id = (tid + it * 256) * 4;
        int n = id >> 6, c = id & 63;
        *(uint2*)&g_xh[((size_t)b * HW + n0 + n) * C + c0 + c] = *(const uint2*)&sh[n][c];
    }
}

// ---------------------------------------------------------------------------
// 2. QKV projection via fp16 MMA. CTA: 128 n-rows x 64 d, K=512 (8 chunks of
//    64, cp.async double-buffered). grid.z picks q/k/v.
// ---------------------------------------------------------------------------
#define PJ_XT 0
#define PJ_XBUF 18432
#define PJ_WT 36864
#define PJ_WBUF 9216
#define PROJ_SMEM 55296

__global__ void __launch_bounds__(256, 1) proj_kernel(
        const float* __restrict__ bq, const float* __restrict__ bk,
        const float* __restrict__ bv) {
    extern __shared__ char smem[];
    const uint32_t sb = smem_u32(smem);
    const int tid = threadIdx.x, wid = tid >> 5, lane = tid & 31;
    const int g = lane >> 2, t = lane & 3;
    const int which = blockIdx.z, b = blockIdx.y;
    const int n0 = blockIdx.x * 128;
    const __half* wh = (which == 0) ? g_wqh : (which == 1) ? g_wkh : g_wvh;
    const float* bias = (which == 0) ? bq : (which == 1) ? bk : bv;
    const __half* xb = g_xh + (size_t)(b * HW + n0) * C;

    // prologue: chunk 0
    for (int i = tid; i < 1024; i += 256) {
        int r = i >> 3, ch = i & 7;
        cp16(sb + PJ_XT + r * 144 + ch * 16, xb + (size_t)r * C + ch * 8);
    }
    for (int i = tid; i < 512; i += 256) {
        int r = i >> 3, ch = i & 7;
        cp16(sb + PJ_WT + r * 144 + ch * 16, wh + r * C + ch * 8);
    }
    cp_commit();
    cp_wait0();
    __syncthreads();

    float acc[8][4];
#pragma unroll
    for (int j = 0; j < 8; j++)
#pragma unroll
        for (int k = 0; k < 4; k++) acc[j][k] = 0.f;

    for (int kc = 0; kc < 8; kc++) {
        int buf = kc & 1;
        if (kc < 7) {
            int k1 = (kc + 1) * 64;
            int nb = buf ^ 1;
            for (int i = tid; i < 1024; i += 256) {
                int r = i >> 3, ch = i & 7;
                cp16(sb + PJ_XT + nb * PJ_XBUF + r * 144 + ch * 16,
                     xb + (size_t)r * C + k1 + ch * 8);
            }
            for (int i = tid; i < 512; i += 256) {
                int r = i >> 3, ch = i & 7;
                cp16(sb + PJ_WT + nb * PJ_WBUF + r * 144 + ch * 16,
                     wh + r * C + k1 + ch * 8);
            }
        }
        cp_commit();

        const char* abase = smem + PJ_XT + buf * PJ_XBUF + (wid * 16 + g) * 144 + t * 4;
        uint32_t qa[4][4];
#pragma unroll
        for (int s = 0; s < 4; s++) {
            qa[s][0] = *(const uint32_t*)(abase + s * 32);
            qa[s][1] = *(const uint32_t*)(abase + 8 * 144 + s * 32);
            qa[s][2] = *(const uint32_t*)(abase + s * 32 + 16);
            qa[s][3] = *(const uint32_t*)(abase + 8 * 144 + s * 32 + 16);
        }
        const char* bbase = smem + PJ_WT + buf * PJ_WBUF + g * 144 + t * 4;
#pragma unroll
        for (int j = 0; j < 8; j++) {
            const char* brow = bbase + 8 * j * 144;
#pragma unroll
            for (int s = 0; s < 4; s++) {
                uint32_t b0 = *(const uint32_t*)(brow + s * 32);
                uint32_t b1 = *(const uint32_t*)(brow + s * 32 + 16);
                mma_f16(acc[j][0], acc[j][1], acc[j][2], acc[j][3],
                        qa[s][0], qa[s][1], qa[s][2], qa[s][3],
                        b0, b1, acc[j][0], acc[j][1], acc[j][2], acc[j][3]);
            }
        }
        if (kc < 7) {
            cp_wait0();
            __syncthreads();
        }
    }

    int nloc = wid * 16 + g;
    if (which < 2) {
        __half* outp = ((which == 0) ? g_qh : g_kh) + (size_t)(b * HW + n0) * D;
        float sc = (which == 0) ? 0.125f : 1.0f;
#pragma unroll
        for (int j = 0; j < 8; j++) {
            int d0 = 8 * j + 2 * t;
            float b0v = bias[d0], b1v = bias[d0 + 1];
            *(uint32_t*)&outp[(size_t)nloc * D + d0] =
                packh2((acc[j][0] + b0v) * sc, (acc[j][1] + b1v) * sc);
            *(uint32_t*)&outp[(size_t)(nloc + 8) * D + d0] =
                packh2((acc[j][2] + b0v) * sc, (acc[j][3] + b1v) * sc);
        }
    } else {
        __syncthreads();  // all warps done reading xt buf0 region
        __half* vst = (__half*)smem;  // [64][136]
#pragma unroll
        for (int j = 0; j < 8; j++) {
            int d0 = 8 * j + 2 * t;
            float b0v = bias[d0], b1v = bias[d0 + 1];
            vst[d0 * 136 + nloc] = __float2half(acc[j][0] + b0v);
            vst[(d0 + 1) * 136 + nloc] = __float2half(acc[j][1] + b1v);
            vst[d0 * 136 + nloc + 8] = __float2half(acc[j][2] + b0v);
            vst[(d0 + 1) * 136 + nloc + 8] = __float2half(acc[j][3] + b1v);
        }
        __syncthreads();
#pragma unroll
        for (int it = 0; it < 4; it++) {
            int idx = tid + it * 256;
            int d = idx >> 4, nn = (idx & 15) * 8;
            *(uint4*)&g_vth[((size_t)b * D + d) * HW + n0 + nn] =
                *(const uint4*)&vst[d * 136 + nn];
        }
    }
}

// ---------------------------------------------------------------------------
// 3. fp16 mma.sync flash attention; output written fp16 to g_aoh.
// ---------------------------------------------------------------------------
#define QPITCH 144
#define KPITCH 144
#define VPITCH 272
#define SQ_OFF 0
#define SK_OFF 18432
#define KBYTES 18432
#define SV_OFF (18432 + 2 * 18432)
#define VBYTES 17408
#define ATTN_SMEM (SV_OFF + 2 * VBYTES)   // 90112

__global__ void __launch_bounds__(256, 1) attn_kernel() {
    extern __shared__ char smem[];
    const uint32_t sb = smem_u32(smem);
    const int tid = threadIdx.x, wid = tid >> 5, lane = tid & 31;
    const int g = lane >> 2, t = lane & 3;
    const int b = blockIdx.y;
    const int n0 = blockIdx.x * 128;

    const __half* qh = g_qh + ((size_t)b * HW + n0) * D;
    const __half* kh = g_kh + (size_t)b * HW * D;
    const __half* vh = g_vth + (size_t)b * D * HW;

    for (int i = tid; i < 1024; i += 256) {
        int r = i >> 3, ch = i & 7;
        cp16(sb + SQ_OFF + r * QPITCH + ch * 16, qh + r * 64 + ch * 8);
    }
    for (int i = tid; i < 1024; i += 256) {
        int r = i >> 3, ch = i & 7;
        cp16(sb + SK_OFF + r * KPITCH + ch * 16, kh + (size_t)r * 64 + ch * 8);
    }
    for (int i = tid; i < 1024; i += 256) {
        int r = i >> 4, ch = i & 15;
        cp16(sb + SV_OFF + r * VPITCH + ch * 16, vh + (size_t)r * HW + ch * 8);
    }
    cp_commit();
    cp_wait0();
    __syncthreads();

    uint32_t qa[4][4];
    {
        const char* qbase = smem + SQ_OFF + (wid * 16 + g) * QPITCH + t * 4;
#pragma unroll
        for (int s = 0; s < 4; s++) {
            qa[s][0] = *(const uint32_t*)(qbase + s * 32);
            qa[s][1] = *(const uint32_t*)(qbase + 8 * QPITCH + s * 32);
            qa[s][2] = *(const uint32_t*)(qbase + s * 32 + 16);
            qa[s][3] = *(const uint32_t*)(qbase + 8 * QPITCH + s * 32 + 16);
        }
    }

    float o[8][4];
#pragma unroll
    for (int j = 0; j < 8; j++)
#pragma unroll
        for (int k = 0; k < 4; k++) o[j][k] = 0.f;
    float l0 = 0.f, l1 = 0.f;

    for (int it = 0; it < 32; it++) {
        int buf = it & 1;

        if (it + 1 < 32) {
            int t1 = (it + 1) * 128;
            int nb = buf ^ 1;
            for (int i = tid; i < 1024; i += 256) {
                int r = i >> 3, ch = i & 7;
                cp16(sb + SK_OFF + nb * KBYTES + r * KPITCH + ch * 16,
                     kh + (size_t)(t1 + r) * 64 + ch * 8);
            }
            for (int i = tid; i < 1024; i += 256) {
                int r = i >> 4, ch = i & 15;
                cp16(sb + SV_OFF + nb * VBYTES + r * VPITCH + ch * 16,
                     vh + (size_t)r * HW + t1 + ch * 8);
            }
        }
        cp_commit();

        const char* kbase = smem + SK_OFF + buf * KBYTES + g * KPITCH + t * 4;
        const char* vbase = smem + SV_OFF + buf * VBYTES + g * VPITCH + t * 4;

        uint32_t pa[8][4];
#pragma unroll
        for (int j = 0; j < 16; j++) {
            float c0 = 0.f, c1 = 0.f, c2 = 0.f, c3 = 0.f;
            const char* krow = kbase + 8 * j * KPITCH;
#pragma unroll
            for (int s = 0; s < 4; s++) {
                uint32_t b0 = *(const uint32_t*)(krow + s * 32);
                uint32_t b1 = *(const uint32_t*)(krow + s * 32 + 16);
                mma_f16(c0, c1, c2, c3, qa[s][0], qa[s][1], qa[s][2], qa[s][3],
                        b0, b1, c0, c1, c2, c3);
            }
            float p0 = __expf(c0), p1 = __expf(c1);
            float p2 = __expf(c2), p3 = __expf(c3);
            l0 += p0 + p1;
            l1 += p2 + p3;
            pa[j >> 1][(j & 1) * 2 + 0] = packh2(p0, p1);
            pa[j >> 1][(j & 1) * 2 + 1] = packh2(p2, p3);
        }

#pragma unroll
        for (int j = 0; j < 8; j++) {
            const char* vrow = vbase + 8 * j * VPITCH;
#pragma unroll
            for (int s = 0; s < 8; s++) {
                uint32_t b0 = *(const uint32_t*)(vrow + s * 32);
                uint32_t b1 = *(const uint32_t*)(vrow + s * 32 + 16);
                mma_f16(o[j][0], o[j][1], o[j][2], o[j][3],
                        pa[s][0], pa[s][1], pa[s][2], pa[s][3],
                        b0, b1, o[j][0], o[j][1], o[j][2], o[j][3]);
            }
        }

        if (it + 1 < 32) {
            cp_wait0();
            __syncthreads();
        }
    }

    l0 += __shfl_xor_sync(~0u, l0, 1);
    l0 += __shfl_xor_sync(~0u, l0, 2);
    l1 += __shfl_xor_sync(~0u, l1, 1);
    l1 += __shfl_xor_sync(~0u, l1, 2);
    float i0 = 1.f / l0, i1 = 1.f / l1;

    __half* ao = g_aoh + ((size_t)b * HW + n0 + wid * 16) * D;
#pragma unroll
    for (int j = 0; j < 8; j++) {
        *(uint32_t*)&ao[(size_t)g * 64 + 8 * j + 2 * t] =
            packh2(o[j][0] * i0, o[j][1] * i0);
        *(uint32_t*)&ao[(size_t)(g + 8) * 64 + 8 * j + 2 * t] =
            packh2(o[j][2] * i1, o[j][3] * i1);
    }
}

// ---------------------------------------------------------------------------
// 4. Output projection via fp16 MMA + residual.
//    CTA: 64c x 128n, K=64 single shot. Staged fp32 epilogue.
// ---------------------------------------------------------------------------
#define OP_WT 0
#define OP_AT 9216
#define OP_ST 27648
#define OUTP_SMEM 61440

__global__ void __launch_bounds__(256, 1) outproj_kernel(
        const float* __restrict__ x,
        const float* __restrict__ bo,
        float* __restrict__ out) {
    extern __shared__ char smem[];
    const uint32_t sb = smem_u32(smem);
    const int tid = threadIdx.x, wid = tid >> 5, lane = tid & 31;
    const int g = lane >> 2, t = lane & 3;
    const int b = blockIdx.z;
    const int c0 = blockIdx.y * 64;
    const int n0 = blockIdx.x * 128;

    for (int i = tid; i < 512; i += 256) {
        int r = i >> 3, ch = i & 7;
        cp16(sb + OP_WT + r * 144 + ch * 16, g_woh + (size_t)(c0 + r) * 64 + ch * 8);
    }
    for (int i = tid; i < 1024; i += 256) {
        int r = i >> 3, ch = i & 7;
        cp16(sb + OP_AT + r * 144 + ch * 16,
             g_aoh + ((size_t)b * HW + n0 + r) * 64 + ch * 8);
    }
    cp_commit();
    cp_wait0();
    __syncthreads();

    const int wc = wid & 3, wn = wid >> 2;
    const char* abase = smem + OP_WT + (wc * 16 + g) * 144 + t * 4;
    uint32_t qa[4][4];
#pragma unroll
    for (int s = 0; s < 4; s++) {
        qa[s][0] = *(const uint32_t*)(abase + s * 32);
        qa[s][1] = *(const uint32_t*)(abase + 8 * 144 + s * 32);
        qa[s][2] = *(const uint32_t*)(abase + s * 32 + 16);
        qa[s][3] = *(const uint32_t*)(abase + 8 * 144 + s * 32 + 16);
    }
    const char* bbase = smem + OP_AT + (wn * 64 + g) * 144 + t * 4;

    float acc[8][4];
#pragma unroll
    for (int j = 0; j < 8; j++)
#pragma unroll
        for (int k = 0; k < 4; k++) acc[j][k] = 0.f;

#pragma unroll
    for (int j = 0; j < 8; j++) {
        const char* brow = bbase + 8 * j * 144;
#pragma unroll
        for (int s = 0; s < 4; s++) {
            uint32_t b0 = *(const uint32_t*)(brow + s * 32);
            uint32_t b1 = *(const uint32_t*)(brow + s * 32 + 16);
            mma_f16(acc[j][0], acc[j][1], acc[j][2], acc[j][3],
                    qa[s][0], qa[s][1], qa[s][2], qa[s][3],
                    b0, b1, acc[j][0], acc[j][1], acc[j][2], acc[j][3]);
        }
    }

    // stage fp32 result [64c][132]
    float* st = (float*)(smem + OP_ST);
    int cl = wc * 16 + g;
#pragma unroll
    for (int j = 0; j < 8; j++) {
        int nl = wn * 64 + 8 * j + 2 * t;
        st[cl * 132 + nl] = acc[j][0];
        st[cl * 132 + nl + 1] = acc[j][1];
        st[(cl + 8) * 132 + nl] = acc[j][2];
        st[(cl + 8) * 132 + nl + 1] = acc[j][3];
    }
    __syncthreads();

#pragma unroll
    for (int it = 0; it < 8; it++) {
        int idx = tid + it * 256;
        int c = idx >> 5, n4 = (idx & 31) * 4;
        size_t gi = ((size_t)b * C + c0 + c) * HW + n0 + n4;
        float bi = bo[c0 + c];
        float4 xr = *(const float4*)&x[gi];
        float4 s4 = *(const float4*)&st[c * 132 + n4];
        float4 r;
        r.x = s4.x + bi + xr.x;
        r.y = s4.y + bi + xr.y;
        r.z = s4.z + bi + xr.z;
        r.w = s4.w + bi + xr.w;
        *(float4*)&out[gi] = r;
    }
}

// ---------------------------------------------------------------------------
extern "C" void kernel_launch(void* const* d_in, const int* in_sizes, int n_in,
                              void* d_out, int out_size) {
    const float* x     = (const float*)d_in[0];
    const float* gamma = (const float*)d_in[1];
    const float* beta  = (const float*)d_in[2];
    const float* wq    = (const float*)d_in[3];
    const float* bq    = (const float*)d_in[4];
    const float* wk    = (const float*)d_in[5];
    const float* bk    = (const float*)d_in[6];
    const float* wv    = (const float*)d_in[7];
    const float* bv    = (const float*)d_in[8];
    const float* wo    = (const float*)d_in[9];
    const float* bo    = (const float*)d_in[10];
    float* out = (float*)d_out;

    static int attr_done = 0;
    if (!attr_done) {
        cudaFuncSetAttribute(attn_kernel, cudaFuncAttributeMaxDynamicSharedMemorySize,
                             ATTN_SMEM);
        cudaFuncSetAttribute(proj_kernel, cudaFuncAttributeMaxDynamicSharedMemorySize,
                             PROJ_SMEM);
        cudaFuncSetAttribute(outproj_kernel, cudaFuncAttributeMaxDynamicSharedMemorySize,
                             OUTP_SMEM);
        attr_done = 1;
    }

    gn_stats_kernel<<<BB * GROUPS, 512>>>(x, gamma, beta);
    wcvt_kernel<<<32, 256>>>(wq, wk, wv, wo);
    gn_apply_kernel<<<dim3(HW / 64, C / 64, BB), 256>>>(x);
    proj_kernel<<<dim3(HW / 128, BB, 3), 256, PROJ_SMEM>>>(bq, bk, bv);
    attn_kernel<<<dim3(HW / 128, BB), 256, ATTN_SMEM>>>();
    outproj_kernel<<<dim3(HW / 128, C / 64, BB), 256, OUTP_SMEM>>>(x, bo, out);
}

// round 6
// speedup vs baseline: 11.5952x; 1.5289x over previous
#include <cuda_runtime.h>
#include <cuda_fp16.h>
#include <cstdint>

#define BB 4
#define C 512
#define D 64
#define HW 4096
#define GROUPS 32
#define CPG 16
#define EPS 1e-5f

// Scratch (device globals — no allocation allowed)
__device__ float g_scale[BB * C];
__device__ float g_bias[BB * C];
__device__ __half g_xh[BB * HW * C];     // normalized x, transposed [B,N,C] fp16
__device__ __half g_wqh[D * C], g_wkh[D * C], g_wvh[D * C], g_woh[C * D];
__device__ __half g_qh[BB * HW * D];     // [B,N,D] fp16, pre-scaled by 0.125*log2e
__device__ __half g_kh[BB * HW * D];     // [B,N,D] fp16
__device__ __half g_vth[BB * D * HW];    // [B,D,N] fp16
__device__ __half g_aoh[BB * HW * D];    // attention output [B,N,D] fp16

// ---------------------------------------------------------------------------
// helpers
// ---------------------------------------------------------------------------
__device__ __forceinline__ uint32_t smem_u32(const void* p) {
    uint32_t a;
    asm("{ .reg .u64 t; cvta.to.shared.u64 t, %1; cvt.u32.u64 %0, t; }" : "=r"(a) : "l"(p));
    return a;
}
__device__ __forceinline__ void cp16(uint32_t s, const void* g) {
    asm volatile("cp.async.cg.shared.global [%0], [%1], 16;" :: "r"(s), "l"(g));
}
__device__ __forceinline__ void cp_commit() { asm volatile("cp.async.commit_group;"); }
__device__ __forceinline__ void cp_wait0() { asm volatile("cp.async.wait_group 0;" ::: "memory"); }

__device__ __forceinline__ void mma_f16(float& d0, float& d1, float& d2, float& d3,
                                        uint32_t a0, uint32_t a1, uint32_t a2, uint32_t a3,
                                        uint32_t b0, uint32_t b1,
                                        float c0, float c1, float c2, float c3) {
    asm volatile(
        "mma.sync.aligned.m16n8k16.row.col.f32.f16.f16.f32 "
        "{%0,%1,%2,%3},{%4,%5,%6,%7},{%8,%9},{%10,%11,%12,%13};"
        : "=f"(d0), "=f"(d1), "=f"(d2), "=f"(d3)
        : "r"(a0), "r"(a1), "r"(a2), "r"(a3), "r"(b0), "r"(b1),
          "f"(c0), "f"(c1), "f"(c2), "f"(c3));
}
__device__ __forceinline__ void ldsm4(uint32_t& r0, uint32_t& r1, uint32_t& r2, uint32_t& r3,
                                      uint32_t addr) {
    asm volatile("ldmatrix.sync.aligned.m8n8.x4.shared.b16 {%0,%1,%2,%3}, [%4];"
                 : "=r"(r0), "=r"(r1), "=r"(r2), "=r"(r3) : "r"(addr));
}
__device__ __forceinline__ uint32_t packh2(float lo, float hi) {
    __half2 h = __floats2half2_rn(lo, hi);
    return *(uint32_t*)&h;
}
__device__ __forceinline__ float ex2(float x) {
    float r;
    asm("ex2.approx.ftz.f32 %0, %1;" : "=f"(r) : "f"(x));
    return r;
}

// ---------------------------------------------------------------------------
// 1. GroupNorm stats
// ---------------------------------------------------------------------------
__global__ void gn_stats_kernel(const float* __restrict__ x,
                                const float* __restrict__ gamma,
                                const float* __restrict__ beta) {
    int bg = blockIdx.x;
    int b = bg / GROUPS, g = bg % GROUPS;
    const float* xp = x + ((size_t)b * C + g * CPG) * HW;
    const int NE = CPG * HW;

    float s = 0.f, ss = 0.f;
    for (int i = threadIdx.x * 4; i < NE; i += blockDim.x * 4) {
        float4 v = *(const float4*)(xp + i);
        s += v.x + v.y + v.z + v.w;
        ss += v.x * v.x + v.y * v.y + v.z * v.z + v.w * v.w;
    }
    __shared__ float sbuf[32], ssbuf[32];
#pragma unroll
    for (int o = 16; o; o >>= 1) {
        s += __shfl_xor_sync(~0u, s, o);
        ss += __shfl_xor_sync(~0u, ss, o);
    }
    int w = threadIdx.x >> 5;
    if ((threadIdx.x & 31) == 0) { sbuf[w] = s; ssbuf[w] = ss; }
    __syncthreads();
    int nw = blockDim.x >> 5;
    if (threadIdx.x < 32) {
        s = threadIdx.x < nw ? sbuf[threadIdx.x] : 0.f;
        ss = threadIdx.x < nw ? ssbuf[threadIdx.x] : 0.f;
#pragma unroll
        for (int o = 16; o; o >>= 1) {
            s += __shfl_xor_sync(~0u, s, o);
            ss += __shfl_xor_sync(~0u, ss, o);
        }
        if (threadIdx.x == 0) { sbuf[0] = s; ssbuf[0] = ss; }
    }
    __syncthreads();
    float mean = sbuf[0] / NE;
    float var = ssbuf[0] / NE - mean * mean;
    float rstd = rsqrtf(var + EPS);

    if (threadIdx.x < CPG) {
        int c = g * CPG + threadIdx.x;
        float ga = gamma[c] * rstd;
        g_scale[b * C + c] = ga;
        g_bias[b * C + c] = beta[c] - mean * ga;
    }
}

// ---------------------------------------------------------------------------
// 1b. Weight convert fp32 -> fp16
// ---------------------------------------------------------------------------
__global__ void wcvt_kernel(const float* __restrict__ wq, const float* __restrict__ wk,
                            const float* __restrict__ wv, const float* __restrict__ wo) {
    int id = (blockIdx.x * 256 + threadIdx.x) * 4;
    if (id < D * C) {
        float4 a;
        a = *(const float4*)&wq[id];
        *(__half2*)&g_wqh[id] = __floats2half2_rn(a.x, a.y);
        *(__half2*)&g_wqh[id + 2] = __floats2half2_rn(a.z, a.w);
        a = *(const float4*)&wk[id];
        *(__half2*)&g_wkh[id] = __floats2half2_rn(a.x, a.y);
        *(__half2*)&g_wkh[id + 2] = __floats2half2_rn(a.z, a.w);
        a = *(const float4*)&wv[id];
        *(__half2*)&g_wvh[id] = __floats2half2_rn(a.x, a.y);
        *(__half2*)&g_wvh[id + 2] = __floats2half2_rn(a.z, a.w);
        a = *(const float4*)&wo[id];
        *(__half2*)&g_woh[id] = __floats2half2_rn(a.x, a.y);
        *(__half2*)&g_woh[id + 2] = __floats2half2_rn(a.z, a.w);
    }
}

// ---------------------------------------------------------------------------
// 1c. GN apply + transpose: x[b][c][n] fp32 -> xh[b][n][c] fp16
// ---------------------------------------------------------------------------
__global__ void __launch_bounds__(256) gn_apply_kernel(const float* __restrict__ x) {
    __shared__ __half sh[64][72];
    __shared__ float sga[64], sbe[64];
    int b = blockIdx.z, c0 = blockIdx.y * 64, n0 = blockIdx.x * 64;
    int tid = threadIdx.x;

    if (tid < 64) {
        sga[tid] = g_scale[b * C + c0 + tid];
        sbe[tid] = g_bias[b * C + c0 + tid];
    }
    __syncthreads();

#pragma unroll
    for (int it = 0; it < 4; it++) {
        int id = (tid + it * 256) * 4;
        int c = id >> 6, n = id & 63;
        float ga = sga[c], be = sbe[c];
        float4 v = *(const float4*)&x[((size_t)b * C + c0 + c) * HW + n0 + n];
        sh[n + 0][c] = __float2half(v.x * ga + be);
        sh[n + 1][c] = __float2half(v.y * ga + be);
        sh[n + 2][c] = __float2half(v.z * ga + be);
        sh[n + 3][c] = __float2half(v.w * ga + be);
    }
    __syncthreads();

#pragma unroll
    for (int it = 0; it < 4; it++) {
        int id = (tid + it * 256) * 4;
        int n = id >> 6, c = id & 63;
        *(uint2*)&g_xh[((size_t)b * HW + n0 + n) * C + c0 + c] = *(const uint2*)&sh[n][c];
    }
}

// ---------------------------------------------------------------------------
// 2. Fused QKV projection via fp16 MMA. One CTA: 128 n-rows, ALL of q/k/v.
//    K=512 in 8 chunks of 64, double-buffered. grid = (32, BB).
//    SMEM: X dbl 2x18432, W dbl 2x(3*64*144)=2x27648.
// ---------------------------------------------------------------------------
#define PJ_XT 0
#define PJ_XBUF 18432
#define PJ_WT 36864
#define PJ_WBUF 27648
#define PROJ_SMEM 92160

__global__ void __launch_bounds__(256, 1) proj_kernel(
        const float* __restrict__ bq, const float* __restrict__ bk,
        const float* __restrict__ bv) {
    extern __shared__ char smem[];
    const uint32_t sb = smem_u32(smem);
    const int tid = threadIdx.x, wid = tid >> 5, lane = tid & 31;
    const int g = lane >> 2, t = lane & 3;
    const int b = blockIdx.y;
    const int n0 = blockIdx.x * 128;
    const __half* xb = g_xh + (size_t)(b * HW + n0) * C;

    // prologue: chunk 0 — X (128 rows) + W q/k/v (192 rows)
    for (int i = tid; i < 1024; i += 256) {
        int r = i >> 3, ch = i & 7;
        cp16(sb + PJ_XT + r * 144 + ch * 16, xb + (size_t)r * C + ch * 8);
    }
    for (int i = tid; i < 1536; i += 256) {
        int r = i >> 3, ch = i & 7;   // r: 0..63 q, 64..127 k, 128..191 v
        const __half* wsrc = (r < 64) ? g_wqh : (r < 128) ? g_wkh : g_wvh;
        int rr = r & 63;
        cp16(sb + PJ_WT + r * 144 + ch * 16, wsrc + rr * C + ch * 8);
    }
    cp_commit();
    cp_wait0();
    __syncthreads();

    float aq[8][4], ak[8][4], av[8][4];
#pragma unroll
    for (int j = 0; j < 8; j++)
#pragma unroll
        for (int k = 0; k < 4; k++) { aq[j][k] = 0.f; ak[j][k] = 0.f; av[j][k] = 0.f; }

    const uint32_t lmrow = (lane & 7), lmcol = (lane >> 3);

    for (int kc = 0; kc < 8; kc++) {
        int buf = kc & 1;
        if (kc < 7) {
            int k1 = (kc + 1) * 64;
            int nb = buf ^ 1;
            for (int i = tid; i < 1024; i += 256) {
                int r = i >> 3, ch = i & 7;
                cp16(sb + PJ_XT + nb * PJ_XBUF + r * 144 + ch * 16,
                     xb + (size_t)r * C + k1 + ch * 8);
            }
            for (int i = tid; i < 1536; i += 256) {
                int r = i >> 3, ch = i & 7;
                const __half* wsrc = (r < 64) ? g_wqh : (r < 128) ? g_wkh : g_wvh;
                int rr = r & 63;
                cp16(sb + PJ_WT + nb * PJ_WBUF + r * 144 + ch * 16,
                     wsrc + rr * C + k1 + ch * 8);
            }
        }
        cp_commit();

        // A fragments from X (shared across q/k/v)
        const char* abase = smem + PJ_XT + buf * PJ_XBUF + (wid * 16 + g) * 144 + t * 4;
        uint32_t qa[4][4];
#pragma unroll
        for (int s = 0; s < 4; s++) {
            qa[s][0] = *(const uint32_t*)(abase + s * 32);
            qa[s][1] = *(const uint32_t*)(abase + 8 * 144 + s * 32);
            qa[s][2] = *(const uint32_t*)(abase + s * 32 + 16);
            qa[s][3] = *(const uint32_t*)(abase + 8 * 144 + s * 32 + 16);
        }
        // B via ldmatrix: waddr covers k-halves 0..31 (bytes 0..63) per call
        uint32_t waddr = sb + PJ_WT + buf * PJ_WBUF + lmrow * 144 + lmcol * 16;
#pragma unroll
        for (int o = 0; o < 3; o++) {
            float (*acc)[4] = (o == 0) ? aq : (o == 1) ? ak : av;
            uint32_t wo_base = waddr + o * 64 * 144;
#pragma unroll
            for (int j = 0; j < 8; j++) {
                uint32_t m0, m1, m2, m3, m4, m5, m6, m7;
                ldsm4(m0, m1, m2, m3, wo_base + j * 8 * 144);
                ldsm4(m4, m5, m6, m7, wo_base + j * 8 * 144 + 64);
                mma_f16(acc[j][0], acc[j][1], acc[j][2], acc[j][3],
                        qa[0][0], qa[0][1], qa[0][2], qa[0][3], m0, m1,
                        acc[j][0], acc[j][1], acc[j][2], acc[j][3]);
                mma_f16(acc[j][0], acc[j][1], acc[j][2], acc[j][3],
                        qa[1][0], qa[1][1], qa[1][2], qa[1][3], m2, m3,
                        acc[j][0], acc[j][1], acc[j][2], acc[j][3]);
                mma_f16(acc[j][0], acc[j][1], acc[j][2], acc[j][3],
                        qa[2][0], qa[2][1], qa[2][2], qa[2][3], m4, m5,
                        acc[j][0], acc[j][1], acc[j][2], acc[j][3]);
                mma_f16(acc[j][0], acc[j][1], acc[j][2], acc[j][3],
                        qa[3][0], qa[3][1], qa[3][2], qa[3][3], m6, m7,
                        acc[j][0], acc[j][1], acc[j][2], acc[j][3]);
            }
        }
        if (kc < 7) {
            cp_wait0();
            __syncthreads();
        }
    }

    const int nloc = wid * 16 + g;
    // q (scaled by 0.125*log2e for exp2 softmax) and k: direct stores
    const float QSC = 0.125f * 1.44269504f;
    {
        __half* outp = g_qh + (size_t)(b * HW + n0) * D;
#pragma unroll
        for (int j = 0; j < 8; j++) {
            int d0 = 8 * j + 2 * t;
            float b0v = bq[d0], b1v = bq[d0 + 1];
            *(uint32_t*)&outp[(size_t)nloc * D + d0] =
                packh2((aq[j][0] + b0v) * QSC, (aq[j][1] + b1v) * QSC);
            *(uint32_t*)&outp[(size_t)(nloc + 8) * D + d0] =
                packh2((aq[j][2] + b0v) * QSC, (aq[j][3] + b1v) * QSC);
        }
    }
    {
        __half* outp = g_kh + (size_t)(b * HW + n0) * D;
#pragma unroll
        for (int j = 0; j < 8; j++) {
            int d0 = 8 * j + 2 * t;
            float b0v = bk[d0], b1v = bk[d0 + 1];
            *(uint32_t*)&outp[(size_t)nloc * D + d0] =
                packh2(ak[j][0] + b0v, ak[j][1] + b1v);
            *(uint32_t*)&outp[(size_t)(nloc + 8) * D + d0] =
                packh2(ak[j][2] + b0v, ak[j][3] + b1v);
        }
    }
    // v: transpose via smem staging -> g_vth [B,D,N]
    __syncthreads();
    __half* vst = (__half*)smem;  // [64][136]
#pragma unroll
    for (int j = 0; j < 8; j++) {
        int d0 = 8 * j + 2 * t;
        float b0v = bv[d0], b1v = bv[d0 + 1];
        vst[d0 * 136 + nloc] = __float2half(av[j][0] + b0v);
        vst[(d0 + 1) * 136 + nloc] = __float2half(av[j][1] + b1v);
        vst[d0 * 136 + nloc + 8] = __float2half(av[j][2] + b0v);
        vst[(d0 + 1) * 136 + nloc + 8] = __float2half(av[j][3] + b1v);
    }
    __syncthreads();
#pragma unroll
    for (int it = 0; it < 4; it++) {
        int idx = tid + it * 256;
        int d = idx >> 4, nn = (idx & 15) * 8;
        *(uint4*)&g_vth[((size_t)b * D + d) * HW + n0 + nn] =
            *(const uint4*)&vst[d * 136 + nn];
    }
}

// ---------------------------------------------------------------------------
// 3. fp16 mma.sync flash attention with ldmatrix B-frags + exp2 softmax.
// ---------------------------------------------------------------------------
#define QPITCH 144
#define KPITCH 144
#define VPITCH 272
#define SQ_OFF 0
#define SK_OFF 18432
#define KBYTES 18432
#define SV_OFF (18432 + 2 * 18432)
#define VBYTES 17408
#define ATTN_SMEM (SV_OFF + 2 * VBYTES)   // 90112

__global__ void __launch_bounds__(256, 1) attn_kernel() {
    extern __shared__ char smem[];
    const uint32_t sb = smem_u32(smem);
    const int tid = threadIdx.x, wid = tid >> 5, lane = tid & 31;
    const int g = lane >> 2, t = lane & 3;
    const int b = blockIdx.y;
    const int n0 = blockIdx.x * 128;

    const __half* qh = g_qh + ((size_t)b * HW + n0) * D;
    const __half* kh = g_kh + (size_t)b * HW * D;
    const __half* vh = g_vth + (size_t)b * D * HW;

    for (int i = tid; i < 1024; i += 256) {
        int r = i >> 3, ch = i & 7;
        cp16(sb + SQ_OFF + r * QPITCH + ch * 16, qh + r * 64 + ch * 8);
    }
    for (int i = tid; i < 1024; i += 256) {
        int r = i >> 3, ch = i & 7;
        cp16(sb + SK_OFF + r * KPITCH + ch * 16, kh + (size_t)r * 64 + ch * 8);
    }
    for (int i = tid; i < 1024; i += 256) {
        int r = i >> 4, ch = i & 15;
        cp16(sb + SV_OFF + r * VPITCH + ch * 16, vh + (size_t)r * HW + ch * 8);
    }
    cp_commit();
    cp_wait0();
    __syncthreads();

    uint32_t qa[4][4];
    {
        const char* qbase = smem + SQ_OFF + (wid * 16 + g) * QPITCH + t * 4;
#pragma unroll
        for (int s = 0; s < 4; s++) {
            qa[s][0] = *(const uint32_t*)(qbase + s * 32);
            qa[s][1] = *(const uint32_t*)(qbase + 8 * QPITCH + s * 32);
            qa[s][2] = *(const uint32_t*)(qbase + s * 32 + 16);
            qa[s][3] = *(const uint32_t*)(qbase + 8 * QPITCH + s * 32 + 16);
        }
    }

    float o[8][4];
#pragma unroll
    for (int j = 0; j < 8; j++)
#pragma unroll
        for (int k = 0; k < 4; k++) o[j][k] = 0.f;
    float l0 = 0.f, l1 = 0.f;

    const uint32_t lmrow = (lane & 7), lmcol = (lane >> 3);

    for (int it = 0; it < 32; it++) {
        int buf = it & 1;

        if (it + 1 < 32) {
            int t1 = (it + 1) * 128;
            int nb = buf ^ 1;
            for (int i = tid; i < 1024; i += 256) {
                int r = i >> 3, ch = i & 7;
                cp16(sb + SK_OFF + nb * KBYTES + r * KPITCH + ch * 16,
                     kh + (size_t)(t1 + r) * 64 + ch * 8);
            }
            for (int i = tid; i < 1024; i += 256) {
                int r = i >> 4, ch = i & 15;
                cp16(sb + SV_OFF + nb * VBYTES + r * VPITCH + ch * 16,
                     vh + (size_t)r * HW + t1 + ch * 8);
            }
        }
        cp_commit();

        uint32_t kaddr = sb + SK_OFF + buf * KBYTES + lmrow * KPITCH + lmcol * 16;
        uint32_t vaddr = sb + SV_OFF + buf * VBYTES + lmrow * VPITCH + lmcol * 16;

        uint32_t pa[8][4];
#pragma unroll
        for (int j = 0; j < 16; j++) {
            float c0 = 0.f, c1 = 0.f, c2 = 0.f, c3 = 0.f;
            uint32_t kj = kaddr + j * 8 * KPITCH;
            uint32_t m0, m1, m2, m3, m4, m5, m6, m7;
            ldsm4(m0, m1, m2, m3, kj);
            ldsm4(m4, m5, m6, m7, kj + 64);
            mma_f16(c0, c1, c2, c3, qa[0][0], qa[0][1], qa[0][2], qa[0][3],
                    m0, m1, c0, c1, c2, c3);
            mma_f16(c0, c1, c2, c3, qa[1][0], qa[1][1], qa[1][2], qa[1][3],
                    m2, m3, c0, c1, c2, c3);
            mma_f16(c0, c1, c2, c3, qa[2][0], qa[2][1], qa[2][2], qa[2][3],
                    m4, m5, c0, c1, c2, c3);
            mma_f16(c0, c1, c2, c3, qa[3][0], qa[3][1], qa[3][2], qa[3][3],
                    m6, m7, c0, c1, c2, c3);
            float p0 = ex2(c0), p1 = ex2(c1);
            float p2 = ex2(c2), p3 = ex2(c3);
            l0 += p0 + p1;
            l1 += p2 + p3;
            pa[j >> 1][(j & 1) * 2 + 0] = packh2(p0, p1);
            pa[j >> 1][(j & 1) * 2 + 1] = packh2(p2, p3);
        }

#pragma unroll
        for (int j = 0; j < 8; j++) {
            uint32_t vj = vaddr + j * 8 * VPITCH;
            uint32_t m0, m1, m2, m3;
#pragma unroll
            for (int h = 0; h < 4; h++) {
                ldsm4(m0, m1, m2, m3, vj + h * 64);
                mma_f16(o[j][0], o[j][1], o[j][2], o[j][3],
                        pa[2 * h][0], pa[2 * h][1], pa[2 * h][2], pa[2 * h][3],
                        m0, m1, o[j][0], o[j][1], o[j][2], o[j][3]);
                mma_f16(o[j][0], o[j][1], o[j][2], o[j][3],
                        pa[2 * h + 1][0], pa[2 * h + 1][1], pa[2 * h + 1][2], pa[2 * h + 1][3],
                        m2, m3, o[j][0], o[j][1], o[j][2], o[j][3]);
            }
        }

        if (it + 1 < 32) {
            cp_wait0();
            __syncthreads();
        }
    }

    l0 += __shfl_xor_sync(~0u, l0, 1);
    l0 += __shfl_xor_sync(~0u, l0, 2);
    l1 += __shfl_xor_sync(~0u, l1, 1);
    l1 += __shfl_xor_sync(~0u, l1, 2);
    float i0 = 1.f / l0, i1 = 1.f / l1;

    __half* ao = g_aoh + ((size_t)b * HW + n0 + wid * 16) * D;
#pragma unroll
    for (int j = 0; j < 8; j++) {
        *(uint32_t*)&ao[(size_t)g * 64 + 8 * j + 2 * t] =
            packh2(o[j][0] * i0, o[j][1] * i0);
        *(uint32_t*)&ao[(size_t)(g + 8) * 64 + 8 * j + 2 * t] =
            packh2(o[j][2] * i1, o[j][3] * i1);
    }
}

// ---------------------------------------------------------------------------
// 4. Output projection via fp16 MMA + residual (ldmatrix B-frags).
// ---------------------------------------------------------------------------
#define OP_WT 0
#define OP_AT 9216
#define OP_ST 27648
#define OUTP_SMEM 61440

__global__ void __launch_bounds__(256, 1) outproj_kernel(
        const float* __restrict__ x,
        const float* __restrict__ bo,
        float* __restrict__ out) {
    extern __shared__ char smem[];
    const uint32_t sb = smem_u32(smem);
    const int tid = threadIdx.x, wid = tid >> 5, lane = tid & 31;
    const int g = lane >> 2, t = lane & 3;
    const int b = blockIdx.z;
    const int c0 = blockIdx.y * 64;
    const int n0 = blockIdx.x * 128;

    for (int i = tid; i < 512; i += 256) {
        int r = i >> 3, ch = i & 7;
        cp16(sb + OP_WT + r * 144 + ch * 16, g_woh + (size_t)(c0 + r) * 64 + ch * 8);
    }
    for (int i = tid; i < 1024; i += 256) {
        int r = i >> 3, ch = i & 7;
        cp16(sb + OP_AT + r * 144 + ch * 16,
             g_aoh + ((size_t)b * HW + n0 + r) * 64 + ch * 8);
    }
    cp_commit();
    cp_wait0();
    __syncthreads();

    const int wc = wid & 3, wn = wid >> 2;
    const char* abase = smem + OP_WT + (wc * 16 + g) * 144 + t * 4;
    uint32_t qa[4][4];
#pragma unroll
    for (int s = 0; s < 4; s++) {
        qa[s][0] = *(const uint32_t*)(abase + s * 32);
        qa[s][1] = *(const uint32_t*)(abase + 8 * 144 + s * 32);
        qa[s][2] = *(const uint32_t*)(abase + s * 32 + 16);
        qa[s][3] = *(const uint32_t*)(abase + 8 * 144 + s * 32 + 16);
    }
    const uint32_t lmrow = (lane & 7), lmcol = (lane >> 3);
    uint32_t bbase = sb + OP_AT + (wn * 64) * 144 + lmrow * 144 + lmcol * 16;

    float acc[8][4];
#pragma unroll
    for (int j = 0; j < 8; j++)
#pragma unroll
        for (int k = 0; k < 4; k++) acc[j][k] = 0.f;

#pragma unroll
    for (int j = 0; j < 8; j++) {
        uint32_t bj = bbase + j * 8 * 144;
        uint32_t m0, m1, m2, m3, m4, m5, m6, m7;
        ldsm4(m0, m1, m2, m3, bj);
        ldsm4(m4, m5, m6, m7, bj + 64);
        mma_f16(acc[j][0], acc[j][1], acc[j][2], acc[j][3],
                qa[0][0], qa[0][1], qa[0][2], qa[0][3], m0, m1,
                acc[j][0], acc[j][1], acc[j][2], acc[j][3]);
        mma_f16(acc[j][0], acc[j][1], acc[j][2], acc[j][3],
                qa[1][0], qa[1][1], qa[1][2], qa[1][3], m2, m3,
                acc[j][0], acc[j][1], acc[j][2], acc[j][3]);
        mma_f16(acc[j][0], acc[j][1], acc[j][2], acc[j][3],
                qa[2][0], qa[2][1], qa[2][2], qa[2][3], m4, m5,
                acc[j][0], acc[j][1], acc[j][2], acc[j][3]);
        mma_f16(acc[j][0], acc[j][1], acc[j][2], acc[j][3],
                qa[3][0], qa[3][1], qa[3][2], qa[3][3], m6, m7,
                acc[j][0], acc[j][1], acc[j][2], acc[j][3]);
    }

    float* st = (float*)(smem + OP_ST);
    int cl = wc * 16 + g;
#pragma unroll
    for (int j = 0; j < 8; j++) {
        int nl = wn * 64 + 8 * j + 2 * t;
        st[cl * 132 + nl] = acc[j][0];
        st[cl * 132 + nl + 1] = acc[j][1];
        st[(cl + 8) * 132 + nl] = acc[j][2];
        st[(cl + 8) * 132 + nl + 1] = acc[j][3];
    }
    __syncthreads();

#pragma unroll
    for (int it = 0; it < 8; it++) {
        int idx = tid + it * 256;
        int c = idx >> 5, n4 = (idx & 31) * 4;
        size_t gi = ((size_t)b * C + c0 + c) * HW + n0 + n4;
        float bi = bo[c0 + c];
        float4 xr = *(const float4*)&x[gi];
        float4 s4 = *(const float4*)&st[c * 132 + n4];
        float4 r;
        r.x = s4.x + bi + xr.x;
        r.y = s4.y + bi + xr.y;
        r.z = s4.z + bi + xr.z;
        r.w = s4.w + bi + xr.w;
        *(float4*)&out[gi] = r;
    }
}

// ---------------------------------------------------------------------------
extern "C" void kernel_launch(void* const* d_in, const int* in_sizes, int n_in,
                              void* d_out, int out_size) {
    const float* x     = (const float*)d_in[0];
    const float* gamma = (const float*)d_in[1];
    const float* beta  = (const float*)d_in[2];
    const float* wq    = (const float*)d_in[3];
    const float* bq    = (const float*)d_in[4];
    const float* wk    = (const float*)d_in[5];
    const float* bk    = (const float*)d_in[6];
    const float* wv    = (const float*)d_in[7];
    const float* bv    = (const float*)d_in[8];
    const float* wo    = (const float*)d_in[9];
    const float* bo    = (const float*)d_in[10];
    float* out = (float*)d_out;

    static int attr_done = 0;
    if (!attr_done) {
        cudaFuncSetAttribute(attn_kernel, cudaFuncAttributeMaxDynamicSharedMemorySize,
                             ATTN_SMEM);
        cudaFuncSetAttribute(proj_kernel, cudaFuncAttributeMaxDynamicSharedMemorySize,
                             PROJ_SMEM);
        cudaFuncSetAttribute(outproj_kernel, cudaFuncAttributeMaxDynamicSharedMemorySize,
                             OUTP_SMEM);
        attr_done = 1;
    }

    gn_stats_kernel<<<BB * GROUPS, 512>>>(x, gamma, beta);
    wcvt_kernel<<<32, 256>>>(wq, wk, wv, wo);
    gn_apply_kernel<<<dim3(HW / 64, C / 64, BB), 256>>>(x);
    proj_kernel<<<dim3(HW / 128, BB), 256, PROJ_SMEM>>>(bq, bk, bv);
    attn_kernel<<<dim3(HW / 128, BB), 256, ATTN_SMEM>>>();
    outproj_kernel<<<dim3(HW / 128, C / 64, BB), 256, OUTP_SMEM>>>(x, bo, out);
}

// round 7
// speedup vs baseline: 13.0550x; 1.1259x over previous
#include <cuda_runtime.h>
#include <cuda_fp16.h>
#include <cstdint>

#define BB 4
#define C 512
#define D 64
#define HW 4096
#define GROUPS 32
#define CPG 16
#define EPS 1e-5f

// Scratch (device globals — no allocation allowed)
__device__ __half g_xh[BB * HW * C];     // normalized x, transposed [B,N,C] fp16
__device__ __half g_wqh[D * C], g_wkh[D * C], g_wvh[D * C], g_woh[C * D];
__device__ __half g_qh[BB * HW * D];     // [B,N,D] fp16, pre-scaled by 0.125*log2e
__device__ __half g_kh[BB * HW * D];     // [B,N,D] fp16
__device__ __half g_vth[BB * D * HW];    // [B,D,N] fp16
__device__ __half g_aoh[BB * HW * D];    // attention output [B,N,D] fp16

// ---------------------------------------------------------------------------
// helpers
// ---------------------------------------------------------------------------
__device__ __forceinline__ uint32_t smem_u32(const void* p) {
    uint32_t a;
    asm("{ .reg .u64 t; cvta.to.shared.u64 t, %1; cvt.u32.u64 %0, t; }" : "=r"(a) : "l"(p));
    return a;
}
__device__ __forceinline__ void cp16(uint32_t s, const void* g) {
    asm volatile("cp.async.cg.shared.global [%0], [%1], 16;" :: "r"(s), "l"(g));
}
__device__ __forceinline__ void cp_commit() { asm volatile("cp.async.commit_group;"); }
__device__ __forceinline__ void cp_wait0() { asm volatile("cp.async.wait_group 0;" ::: "memory"); }

__device__ __forceinline__ void mma_f16(float& d0, float& d1, float& d2, float& d3,
                                        uint32_t a0, uint32_t a1, uint32_t a2, uint32_t a3,
                                        uint32_t b0, uint32_t b1,
                                        float c0, float c1, float c2, float c3) {
    asm volatile(
        "mma.sync.aligned.m16n8k16.row.col.f32.f16.f16.f32 "
        "{%0,%1,%2,%3},{%4,%5,%6,%7},{%8,%9},{%10,%11,%12,%13};"
        : "=f"(d0), "=f"(d1), "=f"(d2), "=f"(d3)
        : "r"(a0), "r"(a1), "r"(a2), "r"(a3), "r"(b0), "r"(b1),
          "f"(c0), "f"(c1), "f"(c2), "f"(c3));
}
__device__ __forceinline__ void ldsm4(uint32_t& r0, uint32_t& r1, uint32_t& r2, uint32_t& r3,
                                      uint32_t addr) {
    asm volatile("ldmatrix.sync.aligned.m8n8.x4.shared.b16 {%0,%1,%2,%3}, [%4];"
                 : "=r"(r0), "=r"(r1), "=r"(r2), "=r"(r3) : "r"(addr));
}
__device__ __forceinline__ uint32_t packh2(float lo, float hi) {
    __half2 h = __floats2half2_rn(lo, hi);
    return *(uint32_t*)&h;
}
// pack two fp32 scores into f16x2 and exp2 them in one MUFU op
__device__ __forceinline__ uint32_t ex2_h2(float lo, float hi) {
    uint32_t s, p;
    asm("cvt.rn.f16x2.f32 %0, %1, %2;" : "=r"(s) : "f"(hi), "f"(lo));
    asm("ex2.approx.f16x2 %0, %1;" : "=r"(p) : "r"(s));
    return p;
}

// ---------------------------------------------------------------------------
// 1. Fused GroupNorm (stats + apply + transpose to fp16) and weight convert.
//    Blocks 0..127: one per (b, group). Blocks 128..143: weight fp32->fp16.
// ---------------------------------------------------------------------------
__global__ void __launch_bounds__(512) gn_fused_kernel(
        const float* __restrict__ x,
        const float* __restrict__ gamma, const float* __restrict__ beta,
        const float* __restrict__ wq, const float* __restrict__ wk,
        const float* __restrict__ wv, const float* __restrict__ wo) {
    int tid = threadIdx.x;
    if (blockIdx.x >= BB * GROUPS) {
        // weight conversion: 16 blocks x 512 threads x 4 = 32768 = D*C
        int id = ((blockIdx.x - BB * GROUPS) * 512 + tid) * 4;
        float4 a;
        a = *(const float4*)&wq[id];
        *(__half2*)&g_wqh[id] = __floats2half2_rn(a.x, a.y);
        *(__half2*)&g_wqh[id + 2] = __floats2half2_rn(a.z, a.w);
        a = *(const float4*)&wk[id];
        *(__half2*)&g_wkh[id] = __floats2half2_rn(a.x, a.y);
        *(__half2*)&g_wkh[id + 2] = __floats2half2_rn(a.z, a.w);
        a = *(const float4*)&wv[id];
        *(__half2*)&g_wvh[id] = __floats2half2_rn(a.x, a.y);
        *(__half2*)&g_wvh[id + 2] = __floats2half2_rn(a.z, a.w);
        a = *(const float4*)&wo[id];
        *(__half2*)&g_woh[id] = __floats2half2_rn(a.x, a.y);
        *(__half2*)&g_woh[id + 2] = __floats2half2_rn(a.z, a.w);
        return;
    }

    int bg = blockIdx.x;
    int b = bg / GROUPS, g = bg % GROUPS;
    const float* xp = x + ((size_t)b * C + g * CPG) * HW;
    const int NE = CPG * HW;

    float s = 0.f, ss = 0.f;
    for (int i = tid * 4; i < NE; i += 512 * 4) {
        float4 v = *(const float4*)(xp + i);
        s += v.x + v.y + v.z + v.w;
        ss += v.x * v.x + v.y * v.y + v.z * v.z + v.w * v.w;
    }
    __shared__ float sbuf[32], ssbuf[32];
    __shared__ float sga[CPG], sbe[CPG];
#pragma unroll
    for (int o = 16; o; o >>= 1) {
        s += __shfl_xor_sync(~0u, s, o);
        ss += __shfl_xor_sync(~0u, ss, o);
    }
    int w = tid >> 5;
    if ((tid & 31) == 0) { sbuf[w] = s; ssbuf[w] = ss; }
    __syncthreads();
    if (tid < 32) {
        s = tid < 16 ? sbuf[tid] : 0.f;
        ss = tid < 16 ? ssbuf[tid] : 0.f;
#pragma unroll
        for (int o = 8; o; o >>= 1) {
            s += __shfl_xor_sync(~0u, s, o);
            ss += __shfl_xor_sync(~0u, ss, o);
        }
        if (tid == 0) { sbuf[0] = s; ssbuf[0] = ss; }
    }
    __syncthreads();
    float mean = sbuf[0] / NE;
    float var = ssbuf[0] / NE - mean * mean;
    float rstd = rsqrtf(var + EPS);

    if (tid < CPG) {
        int c = g * CPG + tid;
        float ga = gamma[c] * rstd;
        sga[tid] = ga;
        sbe[tid] = beta[c] - mean * ga;
    }
    __syncthreads();

    // apply + transpose: x[c][n] (L2-hot) -> g_xh[b][n][g*16 + c] fp16
    float lga[CPG], lbe[CPG];
#pragma unroll
    for (int c = 0; c < CPG; c++) { lga[c] = sga[c]; lbe[c] = sbe[c]; }

    for (int n0i = tid * 4; n0i < HW; n0i += 512 * 4) {
        __align__(16) __half tmp[4][CPG];
#pragma unroll
        for (int c = 0; c < CPG; c++) {
            float4 v = *(const float4*)&xp[(size_t)c * HW + n0i];
            tmp[0][c] = __float2half(v.x * lga[c] + lbe[c]);
            tmp[1][c] = __float2half(v.y * lga[c] + lbe[c]);
            tmp[2][c] = __float2half(v.z * lga[c] + lbe[c]);
            tmp[3][c] = __float2half(v.w * lga[c] + lbe[c]);
        }
#pragma unroll
        for (int k = 0; k < 4; k++) {
            __half* dst = g_xh + ((size_t)b * HW + n0i + k) * C + g * CPG;
            ((uint4*)dst)[0] = ((const uint4*)tmp[k])[0];
            ((uint4*)dst)[1] = ((const uint4*)tmp[k])[1];
        }
    }
}

// ---------------------------------------------------------------------------
// 2. Fused QKV projection via fp16 MMA. One CTA: 128 n-rows, ALL of q/k/v.
// ---------------------------------------------------------------------------
#define PJ_XT 0
#define PJ_XBUF 18432
#define PJ_WT 36864
#define PJ_WBUF 27648
#define PROJ_SMEM 92160

__global__ void __launch_bounds__(256, 1) proj_kernel(
        const float* __restrict__ bq, const float* __restrict__ bk,
        const float* __restrict__ bv) {
    extern __shared__ char smem[];
    const uint32_t sb = smem_u32(smem);
    const int tid = threadIdx.x, wid = tid >> 5, lane = tid & 31;
    const int g = lane >> 2, t = lane & 3;
    const int b = blockIdx.y;
    const int n0 = blockIdx.x * 128;
    const __half* xb = g_xh + (size_t)(b * HW + n0) * C;

    for (int i = tid; i < 1024; i += 256) {
        int r = i >> 3, ch = i & 7;
        cp16(sb + PJ_XT + r * 144 + ch * 16, xb + (size_t)r * C + ch * 8);
    }
    for (int i = tid; i < 1536; i += 256) {
        int r = i >> 3, ch = i & 7;
        const __half* wsrc = (r < 64) ? g_wqh : (r < 128) ? g_wkh : g_wvh;
        int rr = r & 63;
        cp16(sb + PJ_WT + r * 144 + ch * 16, wsrc + rr * C + ch * 8);
    }
    cp_commit();
    cp_wait0();
    __syncthreads();

    float aq[8][4], ak[8][4], av[8][4];
#pragma unroll
    for (int j = 0; j < 8; j++)
#pragma unroll
        for (int k = 0; k < 4; k++) { aq[j][k] = 0.f; ak[j][k] = 0.f; av[j][k] = 0.f; }

    const uint32_t lmrow = (lane & 7), lmcol = (lane >> 3);

    for (int kc = 0; kc < 8; kc++) {
        int buf = kc & 1;
        if (kc < 7) {
            int k1 = (kc + 1) * 64;
            int nb = buf ^ 1;
            for (int i = tid; i < 1024; i += 256) {
                int r = i >> 3, ch = i & 7;
                cp16(sb + PJ_XT + nb * PJ_XBUF + r * 144 + ch * 16,
                     xb + (size_t)r * C + k1 + ch * 8);
            }
            for (int i = tid; i < 1536; i += 256) {
                int r = i >> 3, ch = i & 7;
                const __half* wsrc = (r < 64) ? g_wqh : (r < 128) ? g_wkh : g_wvh;
                int rr = r & 63;
                cp16(sb + PJ_WT + nb * PJ_WBUF + r * 144 + ch * 16,
                     wsrc + rr * C + k1 + ch * 8);
            }
        }
        cp_commit();

        const char* abase = smem + PJ_XT + buf * PJ_XBUF + (wid * 16 + g) * 144 + t * 4;
        uint32_t qa[4][4];
#pragma unroll
        for (int s = 0; s < 4; s++) {
            qa[s][0] = *(const uint32_t*)(abase + s * 32);
            qa[s][1] = *(const uint32_t*)(abase + 8 * 144 + s * 32);
            qa[s][2] = *(const uint32_t*)(abase + s * 32 + 16);
            qa[s][3] = *(const uint32_t*)(abase + 8 * 144 + s * 32 + 16);
        }
        uint32_t waddr = sb + PJ_WT + buf * PJ_WBUF + lmrow * 144 + lmcol * 16;
#pragma unroll
        for (int o = 0; o < 3; o++) {
            float (*acc)[4] = (o == 0) ? aq : (o == 1) ? ak : av;
            uint32_t wo_base = waddr + o * 64 * 144;
#pragma unroll
            for (int j = 0; j < 8; j++) {
                uint32_t m0, m1, m2, m3, m4, m5, m6, m7;
                ldsm4(m0, m1, m2, m3, wo_base + j * 8 * 144);
                ldsm4(m4, m5, m6, m7, wo_base + j * 8 * 144 + 64);
                mma_f16(acc[j][0], acc[j][1], acc[j][2], acc[j][3],
                        qa[0][0], qa[0][1], qa[0][2], qa[0][3], m0, m1,
                        acc[j][0], acc[j][1], acc[j][2], acc[j][3]);
                mma_f16(acc[j][0], acc[j][1], acc[j][2], acc[j][3],
                        qa[1][0], qa[1][1], qa[1][2], qa[1][3], m2, m3,
                        acc[j][0], acc[j][1], acc[j][2], acc[j][3]);
                mma_f16(acc[j][0], acc[j][1], acc[j][2], acc[j][3],
                        qa[2][0], qa[2][1], qa[2][2], qa[2][3], m4, m5,
                        acc[j][0], acc[j][1], acc[j][2], acc[j][3]);
                mma_f16(acc[j][0], acc[j][1], acc[j][2], acc[j][3],
                        qa[3][0], qa[3][1], qa[3][2], qa[3][3], m6, m7,
                        acc[j][0], acc[j][1], acc[j][2], acc[j][3]);
            }
        }
        if (kc < 7) {
            cp_wait0();
            __syncthreads();
        }
    }

    const int nloc = wid * 16 + g;
    const float QSC = 0.125f * 1.44269504f;
    {
        __half* outp = g_qh + (size_t)(b * HW + n0) * D;
#pragma unroll
        for (int j = 0; j < 8; j++) {
            int d0 = 8 * j + 2 * t;
            float b0v = bq[d0], b1v = bq[d0 + 1];
            *(uint32_t*)&outp[(size_t)nloc * D + d0] =
                packh2((aq[j][0] + b0v) * QSC, (aq[j][1] + b1v) * QSC);
            *(uint32_t*)&outp[(size_t)(nloc + 8) * D + d0] =
                packh2((aq[j][2] + b0v) * QSC, (aq[j][3] + b1v) * QSC);
        }
    }
    {
        __half* outp = g_kh + (size_t)(b * HW + n0) * D;
#pragma unroll
        for (int j = 0; j < 8; j++) {
            int d0 = 8 * j + 2 * t;
            float b0v = bk[d0], b1v = bk[d0 + 1];
            *(uint32_t*)&outp[(size_t)nloc * D + d0] =
                packh2(ak[j][0] + b0v, ak[j][1] + b1v);
            *(uint32_t*)&outp[(size_t)(nloc + 8) * D + d0] =
                packh2(ak[j][2] + b0v, ak[j][3] + b1v);
        }
    }
    __syncthreads();
    __half* vst = (__half*)smem;  // [64][136]
#pragma unroll
    for (int j = 0; j < 8; j++) {
        int d0 = 8 * j + 2 * t;
        float b0v = bv[d0], b1v = bv[d0 + 1];
        vst[d0 * 136 + nloc] = __float2half(av[j][0] + b0v);
        vst[(d0 + 1) * 136 + nloc] = __float2half(av[j][1] + b1v);
        vst[d0 * 136 + nloc + 8] = __float2half(av[j][2] + b0v);
        vst[(d0 + 1) * 136 + nloc + 8] = __float2half(av[j][3] + b1v);
    }
    __syncthreads();
#pragma unroll
    for (int it = 0; it < 4; it++) {
        int idx = tid + it * 256;
        int d = idx >> 4, nn = (idx & 15) * 8;
        *(uint4*)&g_vth[((size_t)b * D + d) * HW + n0 + nn] =
            *(const uint4*)&vst[d * 136 + nn];
    }
}

// ---------------------------------------------------------------------------
// 3. fp16 mma.sync flash attention. f16x2 exp2 softmax; l via ones-column MMA
//    (V tile has 72 d-rows: row 64 = 1.0 over 128 keys -> o[8] = row sums).
// ---------------------------------------------------------------------------
#define QPITCH 144
#define KPITCH 144
#define VPITCH 272
#define SQ_OFF 0
#define SK_OFF 18432
#define KBYTES 18432
#define SV_OFF (18432 + 2 * 18432)
#define VBYTES (72 * 272)                 // 19584
#define ATTN_SMEM (SV_OFF + 2 * VBYTES)   // 94464

__global__ void __launch_bounds__(256, 1) attn_kernel() {
    extern __shared__ char smem[];
    const uint32_t sb = smem_u32(smem);
    const int tid = threadIdx.x, wid = tid >> 5, lane = tid & 31;
    const int g = lane >> 2, t = lane & 3;
    const int b = blockIdx.y;
    const int n0 = blockIdx.x * 128;

    const __half* qh = g_qh + ((size_t)b * HW + n0) * D;
    const __half* kh = g_kh + (size_t)b * HW * D;
    const __half* vh = g_vth + (size_t)b * D * HW;

    for (int i = tid; i < 1024; i += 256) {
        int r = i >> 3, ch = i & 7;
        cp16(sb + SQ_OFF + r * QPITCH + ch * 16, qh + r * 64 + ch * 8);
    }
    for (int i = tid; i < 1024; i += 256) {
        int r = i >> 3, ch = i & 7;
        cp16(sb + SK_OFF + r * KPITCH + ch * 16, kh + (size_t)r * 64 + ch * 8);
    }
    for (int i = tid; i < 1024; i += 256) {
        int r = i >> 4, ch = i & 15;
        cp16(sb + SV_OFF + r * VPITCH + ch * 16, vh + (size_t)r * HW + ch * 8);
    }
    cp_commit();
    // init ones/zero rows 64..71 of both V buffers (never overwritten)
    for (int i = tid; i < 2 * 8 * 136; i += 256) {
        int bf = i / 1088, rem = i % 1088;
        int row = 64 + rem / 136, col = rem % 136;
        __half val = (row == 64 && col < 128) ? __float2half(1.f) : __float2half(0.f);
        *(__half*)(smem + SV_OFF + bf * VBYTES + row * VPITCH + col * 2) = val;
    }
    cp_wait0();
    __syncthreads();

    uint32_t qa[4][4];
    {
        const char* qbase = smem + SQ_OFF + (wid * 16 + g) * QPITCH + t * 4;
#pragma unroll
        for (int s = 0; s < 4; s++) {
            qa[s][0] = *(const uint32_t*)(qbase + s * 32);
            qa[s][1] = *(const uint32_t*)(qbase + 8 * QPITCH + s * 32);
            qa[s][2] = *(const uint32_t*)(qbase + s * 32 + 16);
            qa[s][3] = *(const uint32_t*)(qbase + 8 * QPITCH + s * 32 + 16);
        }
    }

    float o[9][4];
#pragma unroll
    for (int j = 0; j < 9; j++)
#pragma unroll
        for (int k = 0; k < 4; k++) o[j][k] = 0.f;

    const uint32_t lmrow = (lane & 7), lmcol = (lane >> 3);

    for (int it = 0; it < 32; it++) {
        int buf = it & 1;

        if (it + 1 < 32) {
            int t1 = (it + 1) * 128;
            int nb = buf ^ 1;
            for (int i = tid; i < 1024; i += 256) {
                int r = i >> 3, ch = i & 7;
                cp16(sb + SK_OFF + nb * KBYTES + r * KPITCH + ch * 16,
                     kh + (size_t)(t1 + r) * 64 + ch * 8);
            }
            for (int i = tid; i < 1024; i += 256) {
                int r = i >> 4, ch = i & 15;
                cp16(sb + SV_OFF + nb * VBYTES + r * VPITCH + ch * 16,
                     vh + (size_t)r * HW + t1 + ch * 8);
            }
        }
        cp_commit();

        uint32_t kaddr = sb + SK_OFF + buf * KBYTES + lmrow * KPITCH + lmcol * 16;
        uint32_t vaddr = sb + SV_OFF + buf * VBYTES + lmrow * VPITCH + lmcol * 16;

        uint32_t pa[8][4];
#pragma unroll
        for (int j = 0; j < 16; j++) {
            float c0 = 0.f, c1 = 0.f, c2 = 0.f, c3 = 0.f;
            uint32_t kj = kaddr + j * 8 * KPITCH;
            uint32_t m0, m1, m2, m3, m4, m5, m6, m7;
            ldsm4(m0, m1, m2, m3, kj);
            ldsm4(m4, m5, m6, m7, kj + 64);
            mma_f16(c0, c1, c2, c3, qa[0][0], qa[0][1], qa[0][2], qa[0][3],
                    m0, m1, c0, c1, c2, c3);
            mma_f16(c0, c1, c2, c3, qa[1][0], qa[1][1], qa[1][2], qa[1][3],
                    m2, m3, c0, c1, c2, c3);
            mma_f16(c0, c1, c2, c3, qa[2][0], qa[2][1], qa[2][2], qa[2][3],
                    m4, m5, c0, c1, c2, c3);
            mma_f16(c0, c1, c2, c3, qa[3][0], qa[3][1], qa[3][2], qa[3][3],
                    m6, m7, c0, c1, c2, c3);
            pa[j >> 1][(j & 1) * 2 + 0] = ex2_h2(c0, c1);
            pa[j >> 1][(j & 1) * 2 + 1] = ex2_h2(c2, c3);
        }

#pragma unroll
        for (int j = 0; j < 9; j++) {
            uint32_t vj = vaddr + j * 8 * VPITCH;
            uint32_t m0, m1, m2, m3;
#pragma unroll
            for (int h = 0; h < 4; h++) {
                ldsm4(m0, m1, m2, m3, vj + h * 64);
                mma_f16(o[j][0], o[j][1], o[j][2], o[j][3],
                        pa[2 * h][0], pa[2 * h][1], pa[2 * h][2], pa[2 * h][3],
                        m0, m1, o[j][0], o[j][1], o[j][2], o[j][3]);
                mma_f16(o[j][0], o[j][1], o[j][2], o[j][3],
                        pa[2 * h + 1][0], pa[2 * h + 1][1], pa[2 * h + 1][2], pa[2 * h + 1][3],
                        m2, m3, o[j][0], o[j][1], o[j][2], o[j][3]);
            }
        }

        if (it + 1 < 32) {
            cp_wait0();
            __syncthreads();
        }
    }

    // row sums of P live in o[8][0]/o[8][2] of the t==0 lane of each quad
    float l0 = __shfl_sync(~0u, o[8][0], lane & 28);
    float l1 = __shfl_sync(~0u, o[8][2], lane & 28);
    float i0 = 1.f / l0, i1 = 1.f / l1;

    __half* ao = g_aoh + ((size_t)b * HW + n0 + wid * 16) * D;
#pragma unroll
    for (int j = 0; j < 8; j++) {
        *(uint32_t*)&ao[(size_t)g * 64 + 8 * j + 2 * t] =
            packh2(o[j][0] * i0, o[j][1] * i0);
        *(uint32_t*)&ao[(size_t)(g + 8) * 64 + 8 * j + 2 * t] =
            packh2(o[j][2] * i1, o[j][3] * i1);
    }
}

// ---------------------------------------------------------------------------
// 4. Output projection via fp16 MMA + residual (ldmatrix B-frags).
// ---------------------------------------------------------------------------
#define OP_WT 0
#define OP_AT 9216
#define OP_ST 27648
#define OUTP_SMEM 61440

__global__ void __launch_bounds__(256, 1) outproj_kernel(
        const float* __restrict__ x,
        const float* __restrict__ bo,
        float* __restrict__ out) {
    extern __shared__ char smem[];
    const uint32_t sb = smem_u32(smem);
    const int tid = threadIdx.x, wid = tid >> 5, lane = tid & 31;
    const int g = lane >> 2, t = lane & 3;
    const int b = blockIdx.z;
    const int c0 = blockIdx.y * 64;
    const int n0 = blockIdx.x * 128;

    for (int i = tid; i < 512; i += 256) {
        int r = i >> 3, ch = i & 7;
        cp16(sb + OP_WT + r * 144 + ch * 16, g_woh + (size_t)(c0 + r) * 64 + ch * 8);
    }
    for (int i = tid; i < 1024; i += 256) {
        int r = i >> 3, ch = i & 7;
        cp16(sb + OP_AT + r * 144 + ch * 16,
             g_aoh + ((size_t)b * HW + n0 + r) * 64 + ch * 8);
    }
    cp_commit();
    cp_wait0();
    __syncthreads();

    const int wc = wid & 3, wn = wid >> 2;
    const char* abase = smem + OP_WT + (wc * 16 + g) * 144 + t * 4;
    uint32_t qa[4][4];
#pragma unroll
    for (int s = 0; s < 4; s++) {
        qa[s][0] = *(const uint32_t*)(abase + s * 32);
        qa[s][1] = *(const uint32_t*)(abase + 8 * 144 + s * 32);
        qa[s][2] = *(const uint32_t*)(abase + s * 32 + 16);
        qa[s][3] = *(const uint32_t*)(abase + 8 * 144 + s * 32 + 16);
    }
    const uint32_t lmrow = (lane & 7), lmcol = (lane >> 3);
    uint32_t bbase = sb + OP_AT + (wn * 64) * 144 + lmrow * 144 + lmcol * 16;

    float acc[8][4];
#pragma unroll
    for (int j = 0; j < 8; j++)
#pragma unroll
        for (int k = 0; k < 4; k++) acc[j][k] = 0.f;

#pragma unroll
    for (int j = 0; j < 8; j++) {
        uint32_t bj = bbase + j * 8 * 144;
        uint32_t m0, m1, m2, m3, m4, m5, m6, m7;
        ldsm4(m0, m1, m2, m3, bj);
        ldsm4(m4, m5, m6, m7, bj + 64);
        mma_f16(acc[j][0], acc[j][1], acc[j][2], acc[j][3],
                qa[0][0], qa[0][1], qa[0][2], qa[0][3], m0, m1,
                acc[j][0], acc[j][1], acc[j][2], acc[j][3]);
        mma_f16(acc[j][0], acc[j][1], acc[j][2], acc[j][3],
                qa[1][0], qa[1][1], qa[1][2], qa[1][3], m2, m3,
                acc[j][0], acc[j][1], acc[j][2], acc[j][3]);
        mma_f16(acc[j][0], acc[j][1], acc[j][2], acc[j][3],
                qa[2][0], qa[2][1], qa[2][2], qa[2][3], m4, m5,
                acc[j][0], acc[j][1], acc[j][2], acc[j][3]);
        mma_f16(acc[j][0], acc[j][1], acc[j][2], acc[j][3],
                qa[3][0], qa[3][1], qa[3][2], qa[3][3], m6, m7,
                acc[j][0], acc[j][1], acc[j][2], acc[j][3]);
    }

    float* st = (float*)(smem + OP_ST);
    int cl = wc * 16 + g;
#pragma unroll
    for (int j = 0; j < 8; j++) {
        int nl = wn * 64 + 8 * j + 2 * t;
        st[cl * 132 + nl] = acc[j][0];
        st[cl * 132 + nl + 1] = acc[j][1];
        st[(cl + 8) * 132 + nl] = acc[j][2];
        st[(cl + 8) * 132 + nl + 1] = acc[j][3];
    }
    __syncthreads();

#pragma unroll
    for (int it = 0; it < 8; it++) {
        int idx = tid + it * 256;
        int c = idx >> 5, n4 = (idx & 31) * 4;
        size_t gi = ((size_t)b * C + c0 + c) * HW + n0 + n4;
        float bi = bo[c0 + c];
        float4 xr = *(const float4*)&x[gi];
        float4 s4 = *(const float4*)&st[c * 132 + n4];
        float4 r;
        r.x = s4.x + bi + xr.x;
        r.y = s4.y + bi + xr.y;
        r.z = s4.z + bi + xr.z;
        r.w = s4.w + bi + xr.w;
        *(float4*)&out[gi] = r;
    }
}

// ---------------------------------------------------------------------------
extern "C" void kernel_launch(void* const* d_in, const int* in_sizes, int n_in,
                              void* d_out, int out_size) {
    const float* x     = (const float*)d_in[0];
    const float* gamma = (const float*)d_in[1];
    const float* beta  = (const float*)d_in[2];
    const float* wq    = (const float*)d_in[3];
    const float* bq    = (const float*)d_in[4];
    const float* wk    = (const float*)d_in[5];
    const float* bk    = (const float*)d_in[6];
    const float* wv    = (const float*)d_in[7];
    const float* bv    = (const float*)d_in[8];
    const float* wo    = (const float*)d_in[9];
    const float* bo    = (const float*)d_in[10];
    float* out = (float*)d_out;

    static int attr_done = 0;
    if (!attr_done) {
        cudaFuncSetAttribute(attn_kernel, cudaFuncAttributeMaxDynamicSharedMemorySize,
                             ATTN_SMEM);
        cudaFuncSetAttribute(proj_kernel, cudaFuncAttributeMaxDynamicSharedMemorySize,
                             PROJ_SMEM);
        cudaFuncSetAttribute(outproj_kernel, cudaFuncAttributeMaxDynamicSharedMemorySize,
                             OUTP_SMEM);
        attr_done = 1;
    }

    gn_fused_kernel<<<BB * GROUPS + 16, 512>>>(x, gamma, beta, wq, wk, wv, wo);
    proj_kernel<<<dim3(HW / 128, BB), 256, PROJ_SMEM>>>(bq, bk, bv);
    attn_kernel<<<dim3(HW / 128, BB), 256, ATTN_SMEM>>>();
    outproj_kernel<<<dim3(HW / 128, C / 64, BB), 256, OUTP_SMEM>>>(x, bo, out);
}

// round 8
// speedup vs baseline: 13.2691x; 1.0164x over previous
#include <cuda_runtime.h>
#include <cuda_fp16.h>
#include <cstdint>

#define BB 4
#define C 512
#define D 64
#define HW 4096
#define GROUPS 32
#define CPG 16
#define EPS 1e-5f

// Scratch (device globals — no allocation allowed)
__device__ __half g_xh[BB * HW * C];     // normalized x, transposed [B,N,C] fp16
__device__ __half g_wqh[D * C], g_wkh[D * C], g_wvh[D * C], g_woh[C * D];
__device__ __half g_qh[BB * HW * D];     // [B,N,D] fp16, pre-scaled by 0.125*log2e
__device__ __half g_kh[BB * HW * D];     // [B,N,D] fp16
__device__ __half g_vth[BB * D * HW];    // [B,D,N] fp16
__device__ __half g_aoh[BB * HW * D];    // attention output [B,N,D] fp16

// ---------------------------------------------------------------------------
// helpers
// ---------------------------------------------------------------------------
__device__ __forceinline__ uint32_t smem_u32(const void* p) {
    uint32_t a;
    asm("{ .reg .u64 t; cvta.to.shared.u64 t, %1; cvt.u32.u64 %0, t; }" : "=r"(a) : "l"(p));
    return a;
}
__device__ __forceinline__ void cp16(uint32_t s, const void* g) {
    asm volatile("cp.async.cg.shared.global [%0], [%1], 16;" :: "r"(s), "l"(g));
}
__device__ __forceinline__ void cp_commit() { asm volatile("cp.async.commit_group;"); }
__device__ __forceinline__ void cp_wait0() { asm volatile("cp.async.wait_group 0;" ::: "memory"); }

__device__ __forceinline__ void mma_f16(float& d0, float& d1, float& d2, float& d3,
                                        uint32_t a0, uint32_t a1, uint32_t a2, uint32_t a3,
                                        uint32_t b0, uint32_t b1,
                                        float c0, float c1, float c2, float c3) {
    asm volatile(
        "mma.sync.aligned.m16n8k16.row.col.f32.f16.f16.f32 "
        "{%0,%1,%2,%3},{%4,%5,%6,%7},{%8,%9},{%10,%11,%12,%13};"
        : "=f"(d0), "=f"(d1), "=f"(d2), "=f"(d3)
        : "r"(a0), "r"(a1), "r"(a2), "r"(a3), "r"(b0), "r"(b1),
          "f"(c0), "f"(c1), "f"(c2), "f"(c3));
}
__device__ __forceinline__ void ldsm4(uint32_t& r0, uint32_t& r1, uint32_t& r2, uint32_t& r3,
                                      uint32_t addr) {
    asm volatile("ldmatrix.sync.aligned.m8n8.x4.shared.b16 {%0,%1,%2,%3}, [%4];"
                 : "=r"(r0), "=r"(r1), "=r"(r2), "=r"(r3) : "r"(addr));
}
__device__ __forceinline__ uint32_t packh2(float lo, float hi) {
    __half2 h = __floats2half2_rn(lo, hi);
    return *(uint32_t*)&h;
}
__device__ __forceinline__ uint32_t ex2_h2(float lo, float hi) {
    uint32_t s, p;
    asm("cvt.rn.f16x2.f32 %0, %1, %2;" : "=r"(s) : "f"(hi), "f"(lo));
    asm("ex2.approx.f16x2 %0, %1;" : "=r"(p) : "r"(s));
    return p;
}

// ---------------------------------------------------------------------------
// 1. Fused GroupNorm (stats + apply + transpose to fp16) and weight convert.
// ---------------------------------------------------------------------------
__global__ void __launch_bounds__(512) gn_fused_kernel(
        const float* __restrict__ x,
        const float* __restrict__ gamma, const float* __restrict__ beta,
        const float* __restrict__ wq, const float* __restrict__ wk,
        const float* __restrict__ wv, const float* __restrict__ wo) {
    int tid = threadIdx.x;
    if (blockIdx.x >= BB * GROUPS) {
        int id = ((blockIdx.x - BB * GROUPS) * 512 + tid) * 4;
        float4 a;
        a = *(const float4*)&wq[id];
        *(__half2*)&g_wqh[id] = __floats2half2_rn(a.x, a.y);
        *(__half2*)&g_wqh[id + 2] = __floats2half2_rn(a.z, a.w);
        a = *(const float4*)&wk[id];
        *(__half2*)&g_wkh[id] = __floats2half2_rn(a.x, a.y);
        *(__half2*)&g_wkh[id + 2] = __floats2half2_rn(a.z, a.w);
        a = *(const float4*)&wv[id];
        *(__half2*)&g_wvh[id] = __floats2half2_rn(a.x, a.y);
        *(__half2*)&g_wvh[id + 2] = __floats2half2_rn(a.z, a.w);
        a = *(const float4*)&wo[id];
        *(__half2*)&g_woh[id] = __floats2half2_rn(a.x, a.y);
        *(__half2*)&g_woh[id + 2] = __floats2half2_rn(a.z, a.w);
        return;
    }

    int bg = blockIdx.x;
    int b = bg / GROUPS, g = bg % GROUPS;
    const float* xp = x + ((size_t)b * C + g * CPG) * HW;
    const int NE = CPG * HW;

    float s = 0.f, ss = 0.f;
    for (int i = tid * 4; i < NE; i += 512 * 4) {
        float4 v = *(const float4*)(xp + i);
        s += v.x + v.y + v.z + v.w;
        ss += v.x * v.x + v.y * v.y + v.z * v.z + v.w * v.w;
    }
    __shared__ float sbuf[32], ssbuf[32];
    __shared__ float sga[CPG], sbe[CPG];
#pragma unroll
    for (int o = 16; o; o >>= 1) {
        s += __shfl_xor_sync(~0u, s, o);
        ss += __shfl_xor_sync(~0u, ss, o);
    }
    int w = tid >> 5;
    if ((tid & 31) == 0) { sbuf[w] = s; ssbuf[w] = ss; }
    __syncthreads();
    if (tid < 32) {
        s = tid < 16 ? sbuf[tid] : 0.f;
        ss = tid < 16 ? ssbuf[tid] : 0.f;
#pragma unroll
        for (int o = 8; o; o >>= 1) {
            s += __shfl_xor_sync(~0u, s, o);
            ss += __shfl_xor_sync(~0u, ss, o);
        }
        if (tid == 0) { sbuf[0] = s; ssbuf[0] = ss; }
    }
    __syncthreads();
    float mean = sbuf[0] / NE;
    float var = ssbuf[0] / NE - mean * mean;
    float rstd = rsqrtf(var + EPS);

    if (tid < CPG) {
        int c = g * CPG + tid;
        float ga = gamma[c] * rstd;
        sga[tid] = ga;
        sbe[tid] = beta[c] - mean * ga;
    }
    __syncthreads();

    float lga[CPG], lbe[CPG];
#pragma unroll
    for (int c = 0; c < CPG; c++) { lga[c] = sga[c]; lbe[c] = sbe[c]; }

    for (int n0i = tid * 4; n0i < HW; n0i += 512 * 4) {
        __align__(16) __half tmp[4][CPG];
#pragma unroll
        for (int c = 0; c < CPG; c++) {
            float4 v = *(const float4*)&xp[(size_t)c * HW + n0i];
            tmp[0][c] = __float2half(v.x * lga[c] + lbe[c]);
            tmp[1][c] = __float2half(v.y * lga[c] + lbe[c]);
            tmp[2][c] = __float2half(v.z * lga[c] + lbe[c]);
            tmp[3][c] = __float2half(v.w * lga[c] + lbe[c]);
        }
#pragma unroll
        for (int k = 0; k < 4; k++) {
            __half* dst = g_xh + ((size_t)b * HW + n0i + k) * C + g * CPG;
            ((uint4*)dst)[0] = ((const uint4*)tmp[k])[0];
            ((uint4*)dst)[1] = ((const uint4*)tmp[k])[1];
        }
    }
}

// ---------------------------------------------------------------------------
// 2. Fused QKV projection via fp16 MMA. 384 threads / 12 warps:
//    warp = (output o = wid>>2) x (m-tile mt = wid&3 -> rows mt*32..mt*32+31).
//    K=512 in 8 chunks of 64, double-buffered.
// ---------------------------------------------------------------------------
#define PJ_XT 0
#define PJ_XBUF 18432
#define PJ_WT 36864
#define PJ_WBUF 27648
#define PROJ_SMEM 92160

__global__ void __launch_bounds__(384, 1) proj_kernel(
        const float* __restrict__ bq, const float* __restrict__ bk,
        const float* __restrict__ bv) {
    extern __shared__ char smem[];
    const uint32_t sb = smem_u32(smem);
    const int tid = threadIdx.x, wid = tid >> 5, lane = tid & 31;
    const int g = lane >> 2, t = lane & 3;
    const int o = wid >> 2, mt = wid & 3;
    const int b = blockIdx.y;
    const int n0 = blockIdx.x * 128;
    const __half* xb = g_xh + (size_t)(b * HW + n0) * C;

    for (int i = tid; i < 1024; i += 384) {
        int r = i >> 3, ch = i & 7;
        cp16(sb + PJ_XT + r * 144 + ch * 16, xb + (size_t)r * C + ch * 8);
    }
    for (int i = tid; i < 1536; i += 384) {
        int r = i >> 3, ch = i & 7;
        const __half* wsrc = (r < 64) ? g_wqh : (r < 128) ? g_wkh : g_wvh;
        int rr = r & 63;
        cp16(sb + PJ_WT + r * 144 + ch * 16, wsrc + rr * C + ch * 8);
    }
    cp_commit();
    cp_wait0();
    __syncthreads();

    float acc[2][8][4];
#pragma unroll
    for (int s = 0; s < 2; s++)
#pragma unroll
        for (int j = 0; j < 8; j++)
#pragma unroll
            for (int k = 0; k < 4; k++) acc[s][j][k] = 0.f;

    const uint32_t lmrow = (lane & 7), lmcol = (lane >> 3);

    for (int kc = 0; kc < 8; kc++) {
        int buf = kc & 1;
        if (kc < 7) {
            int k1 = (kc + 1) * 64;
            int nb = buf ^ 1;
            for (int i = tid; i < 1024; i += 384) {
                int r = i >> 3, ch = i & 7;
                cp16(sb + PJ_XT + nb * PJ_XBUF + r * 144 + ch * 16,
                     xb + (size_t)r * C + k1 + ch * 8);
            }
            for (int i = tid; i < 1536; i += 384) {
                int r = i >> 3, ch = i & 7;
                const __half* wsrc = (r < 64) ? g_wqh : (r < 128) ? g_wkh : g_wvh;
                int rr = r & 63;
                cp16(sb + PJ_WT + nb * PJ_WBUF + r * 144 + ch * 16,
                     wsrc + rr * C + k1 + ch * 8);
            }
        }
        cp_commit();

        // A fragments for the two m16 subtiles of this warp's 32 rows
        uint32_t qa[2][4][4];
#pragma unroll
        for (int s = 0; s < 2; s++) {
            const char* ab = smem + PJ_XT + buf * PJ_XBUF +
                             (mt * 32 + s * 16 + g) * 144 + t * 4;
#pragma unroll
            for (int ks = 0; ks < 4; ks++) {
                qa[s][ks][0] = *(const uint32_t*)(ab + ks * 32);
                qa[s][ks][1] = *(const uint32_t*)(ab + 8 * 144 + ks * 32);
                qa[s][ks][2] = *(const uint32_t*)(ab + ks * 32 + 16);
                qa[s][ks][3] = *(const uint32_t*)(ab + 8 * 144 + ks * 32 + 16);
            }
        }
        uint32_t wbase = sb + PJ_WT + buf * PJ_WBUF + o * 64 * 144 +
                         lmrow * 144 + lmcol * 16;
#pragma unroll
        for (int j = 0; j < 8; j++) {
            uint32_t m0, m1, m2, m3, m4, m5, m6, m7;
            ldsm4(m0, m1, m2, m3, wbase + j * 8 * 144);
            ldsm4(m4, m5, m6, m7, wbase + j * 8 * 144 + 64);
#pragma unroll
            for (int s = 0; s < 2; s++) {
                mma_f16(acc[s][j][0], acc[s][j][1], acc[s][j][2], acc[s][j][3],
                        qa[s][0][0], qa[s][0][1], qa[s][0][2], qa[s][0][3], m0, m1,
                        acc[s][j][0], acc[s][j][1], acc[s][j][2], acc[s][j][3]);
                mma_f16(acc[s][j][0], acc[s][j][1], acc[s][j][2], acc[s][j][3],
                        qa[s][1][0], qa[s][1][1], qa[s][1][2], qa[s][1][3], m2, m3,
                        acc[s][j][0], acc[s][j][1], acc[s][j][2], acc[s][j][3]);
                mma_f16(acc[s][j][0], acc[s][j][1], acc[s][j][2], acc[s][j][3],
                        qa[s][2][0], qa[s][2][1], qa[s][2][2], qa[s][2][3], m4, m5,
                        acc[s][j][0], acc[s][j][1], acc[s][j][2], acc[s][j][3]);
                mma_f16(acc[s][j][0], acc[s][j][1], acc[s][j][2], acc[s][j][3],
                        qa[s][3][0], qa[s][3][1], qa[s][3][2], qa[s][3][3], m6, m7,
                        acc[s][j][0], acc[s][j][1], acc[s][j][2], acc[s][j][3]);
            }
        }
        if (kc < 7) {
            cp_wait0();
            __syncthreads();
        }
    }

    const float QSC = 0.125f * 1.44269504f;
    if (o == 0) {
        __half* outp = g_qh + (size_t)(b * HW + n0) * D;
#pragma unroll
        for (int s = 0; s < 2; s++) {
            int nloc = mt * 32 + s * 16 + g;
#pragma unroll
            for (int j = 0; j < 8; j++) {
                int d0 = 8 * j + 2 * t;
                float b0v = bq[d0], b1v = bq[d0 + 1];
                *(uint32_t*)&outp[(size_t)nloc * D + d0] =
                    packh2((acc[s][j][0] + b0v) * QSC, (acc[s][j][1] + b1v) * QSC);
                *(uint32_t*)&outp[(size_t)(nloc + 8) * D + d0] =
                    packh2((acc[s][j][2] + b0v) * QSC, (acc[s][j][3] + b1v) * QSC);
            }
        }
    } else if (o == 1) {
        __half* outp = g_kh + (size_t)(b * HW + n0) * D;
#pragma unroll
        for (int s = 0; s < 2; s++) {
            int nloc = mt * 32 + s * 16 + g;
#pragma unroll
            for (int j = 0; j < 8; j++) {
                int d0 = 8 * j + 2 * t;
                float b0v = bk[d0], b1v = bk[d0 + 1];
                *(uint32_t*)&outp[(size_t)nloc * D + d0] =
                    packh2(acc[s][j][0] + b0v, acc[s][j][1] + b1v);
                *(uint32_t*)&outp[(size_t)(nloc + 8) * D + d0] =
                    packh2(acc[s][j][2] + b0v, acc[s][j][3] + b1v);
            }
        }
    }
    // v: transpose via smem staging (aliases X buf 0, unused in last chunk)
    __syncthreads();
    __half* vst = (__half*)smem;  // [64][136]
    if (o == 2) {
#pragma unroll
        for (int s = 0; s < 2; s++) {
            int nloc = mt * 32 + s * 16 + g;
#pragma unroll
            for (int j = 0; j < 8; j++) {
                int d0 = 8 * j + 2 * t;
                float b0v = bv[d0], b1v = bv[d0 + 1];
                vst[d0 * 136 + nloc] = __float2half(acc[s][j][0] + b0v);
                vst[(d0 + 1) * 136 + nloc] = __float2half(acc[s][j][1] + b1v);
                vst[d0 * 136 + nloc + 8] = __float2half(acc[s][j][2] + b0v);
                vst[(d0 + 1) * 136 + nloc + 8] = __float2half(acc[s][j][3] + b1v);
            }
        }
    }
    __syncthreads();
    for (int i = tid; i < 1024; i += 384) {
        int d = i >> 4, nn = (i & 15) * 8;
        *(uint4*)&g_vth[((size_t)b * D + d) * HW + n0 + nn] =
            *(const uint4*)&vst[d * 136 + nn];
    }
}

// ---------------------------------------------------------------------------
// 3. fp16 mma.sync flash attention (unchanged from R7).
// ---------------------------------------------------------------------------
#define QPITCH 144
#define KPITCH 144
#define VPITCH 272
#define SQ_OFF 0
#define SK_OFF 18432
#define KBYTES 18432
#define SV_OFF (18432 + 2 * 18432)
#define VBYTES (72 * 272)                 // 19584
#define ATTN_SMEM (SV_OFF + 2 * VBYTES)   // 94464

__global__ void __launch_bounds__(256, 1) attn_kernel() {
    extern __shared__ char smem[];
    const uint32_t sb = smem_u32(smem);
    const int tid = threadIdx.x, wid = tid >> 5, lane = tid & 31;
    const int g = lane >> 2, t = lane & 3;
    const int b = blockIdx.y;
    const int n0 = blockIdx.x * 128;

    const __half* qh = g_qh + ((size_t)b * HW + n0) * D;
    const __half* kh = g_kh + (size_t)b * HW * D;
    const __half* vh = g_vth + (size_t)b * D * HW;

    for (int i = tid; i < 1024; i += 256) {
        int r = i >> 3, ch = i & 7;
        cp16(sb + SQ_OFF + r * QPITCH + ch * 16, qh + r * 64 + ch * 8);
    }
    for (int i = tid; i < 1024; i += 256) {
        int r = i >> 3, ch = i & 7;
        cp16(sb + SK_OFF + r * KPITCH + ch * 16, kh + (size_t)r * 64 + ch * 8);
    }
    for (int i = tid; i < 1024; i += 256) {
        int r = i >> 4, ch = i & 15;
        cp16(sb + SV_OFF + r * VPITCH + ch * 16, vh + (size_t)r * HW + ch * 8);
    }
    cp_commit();
    for (int i = tid; i < 2 * 8 * 136; i += 256) {
        int bf = i / 1088, rem = i % 1088;
        int row = 64 + rem / 136, col = rem % 136;
        __half val = (row == 64 && col < 128) ? __float2half(1.f) : __float2half(0.f);
        *(__half*)(smem + SV_OFF + bf * VBYTES + row * VPITCH + col * 2) = val;
    }
    cp_wait0();
    __syncthreads();

    uint32_t qa[4][4];
    {
        const char* qbase = smem + SQ_OFF + (wid * 16 + g) * QPITCH + t * 4;
#pragma unroll
        for (int s = 0; s < 4; s++) {
            qa[s][0] = *(const uint32_t*)(qbase + s * 32);
            qa[s][1] = *(const uint32_t*)(qbase + 8 * QPITCH + s * 32);
            qa[s][2] = *(const uint32_t*)(qbase + s * 32 + 16);
            qa[s][3] = *(const uint32_t*)(qbase + 8 * QPITCH + s * 32 + 16);
        }
    }

    float o[9][4];
#pragma unroll
    for (int j = 0; j < 9; j++)
#pragma unroll
        for (int k = 0; k < 4; k++) o[j][k] = 0.f;

    const uint32_t lmrow = (lane & 7), lmcol = (lane >> 3);

    for (int it = 0; it < 32; it++) {
        int buf = it & 1;

        if (it + 1 < 32) {
            int t1 = (it + 1) * 128;
            int nb = buf ^ 1;
            for (int i = tid; i < 1024; i += 256) {
                int r = i >> 3, ch = i & 7;
                cp16(sb + SK_OFF + nb * KBYTES + r * KPITCH + ch * 16,
                     kh + (size_t)(t1 + r) * 64 + ch * 8);
            }
            for (int i = tid; i < 1024; i += 256) {
                int r = i >> 4, ch = i & 15;
                cp16(sb + SV_OFF + nb * VBYTES + r * VPITCH + ch * 16,
                     vh + (size_t)r * HW + t1 + ch * 8);
            }
        }
        cp_commit();

        uint32_t kaddr = sb + SK_OFF + buf * KBYTES + lmrow * KPITCH + lmcol * 16;
        uint32_t vaddr = sb + SV_OFF + buf * VBYTES + lmrow * VPITCH + lmcol * 16;

        uint32_t pa[8][4];
#pragma unroll
        for (int j = 0; j < 16; j++) {
            float c0 = 0.f, c1 = 0.f, c2 = 0.f, c3 = 0.f;
            uint32_t kj = kaddr + j * 8 * KPITCH;
            uint32_t m0, m1, m2, m3, m4, m5, m6, m7;
            ldsm4(m0, m1, m2, m3, kj);
            ldsm4(m4, m5, m6, m7, kj + 64);
            mma_f16(c0, c1, c2, c3, qa[0][0], qa[0][1], qa[0][2], qa[0][3],
                    m0, m1, c0, c1, c2, c3);
            mma_f16(c0, c1, c2, c3, qa[1][0], qa[1][1], qa[1][2], qa[1][3],
                    m2, m3, c0, c1, c2, c3);
            mma_f16(c0, c1, c2, c3, qa[2][0], qa[2][1], qa[2][2], qa[2][3],
                    m4, m5, c0, c1, c2, c3);
            mma_f16(c0, c1, c2, c3, qa[3][0], qa[3][1], qa[3][2], qa[3][3],
                    m6, m7, c0, c1, c2, c3);
            pa[j >> 1][(j & 1) * 2 + 0] = ex2_h2(c0, c1);
            pa[j >> 1][(j & 1) * 2 + 1] = ex2_h2(c2, c3);
        }

#pragma unroll
        for (int j = 0; j < 9; j++) {
            uint32_t vj = vaddr + j * 8 * VPITCH;
            uint32_t m0, m1, m2, m3;
#pragma unroll
            for (int h = 0; h < 4; h++) {
                ldsm4(m0, m1, m2, m3, vj + h * 64);
                mma_f16(o[j][0], o[j][1], o[j][2], o[j][3],
                        pa[2 * h][0], pa[2 * h][1], pa[2 * h][2], pa[2 * h][3],
                        m0, m1, o[j][0], o[j][1], o[j][2], o[j][3]);
                mma_f16(o[j][0], o[j][1], o[j][2], o[j][3],
                        pa[2 * h + 1][0], pa[2 * h + 1][1], pa[2 * h + 1][2], pa[2 * h + 1][3],
                        m2, m3, o[j][0], o[j][1], o[j][2], o[j][3]);
            }
        }

        if (it + 1 < 32) {
            cp_wait0();
            __syncthreads();
        }
    }

    float l0 = __shfl_sync(~0u, o[8][0], lane & 28);
    float l1 = __shfl_sync(~0u, o[8][2], lane & 28);
    float i0 = 1.f / l0, i1 = 1.f / l1;

    __half* ao = g_aoh + ((size_t)b * HW + n0 + wid * 16) * D;
#pragma unroll
    for (int j = 0; j < 8; j++) {
        *(uint32_t*)&ao[(size_t)g * 64 + 8 * j + 2 * t] =
            packh2(o[j][0] * i0, o[j][1] * i0);
        *(uint32_t*)&ao[(size_t)(g + 8) * 64 + 8 * j + 2 * t] =
            packh2(o[j][2] * i1, o[j][3] * i1);
    }
}

// ---------------------------------------------------------------------------
// 4. Output projection via fp16 MMA + residual. 2 CTAs/SM; staging buffer
//    aliases the fragment smem (freed after frag loads).
// ---------------------------------------------------------------------------
#define OP_WT 0
#define OP_AT 9216
#define OUTP_SMEM 33792    // max(27648 frags, 64*132*4 staging)

__global__ void __launch_bounds__(256, 2) outproj_kernel(
        const float* __restrict__ x,
        const float* __restrict__ bo,
        float* __restrict__ out) {
    extern __shared__ char smem[];
    const uint32_t sb = smem_u32(smem);
    const int tid = threadIdx.x, wid = tid >> 5, lane = tid & 31;
    const int g = lane >> 2, t = lane & 3;
    const int b = blockIdx.z;
    const int c0 = blockIdx.y * 64;
    const int n0 = blockIdx.x * 128;

    for (int i = tid; i < 512; i += 256) {
        int r = i >> 3, ch = i & 7;
        cp16(sb + OP_WT + r * 144 + ch * 16, g_woh + (size_t)(c0 + r) * 64 + ch * 8);
    }
    for (int i = tid; i < 1024; i += 256) {
        int r = i >> 3, ch = i & 7;
        cp16(sb + OP_AT + r * 144 + ch * 16,
             g_aoh + ((size_t)b * HW + n0 + r) * 64 + ch * 8);
    }
    cp_commit();
    cp_wait0();
    __syncthreads();

    const int wc = wid & 3, wn = wid >> 2;
    const char* abase = smem + OP_WT + (wc * 16 + g) * 144 + t * 4;
    uint32_t qa[4][4];
#pragma unroll
    for (int s = 0; s < 4; s++) {
        qa[s][0] = *(const uint32_t*)(abase + s * 32);
        qa[s][1] = *(const uint32_t*)(abase + 8 * 144 + s * 32);
        qa[s][2] = *(const uint32_t*)(abase + s * 32 + 16);
        qa[s][3] = *(const uint32_t*)(abase + 8 * 144 + s * 32 + 16);
    }
    const uint32_t lmrow = (lane & 7), lmcol = (lane >> 3);
    uint32_t bbase = sb + OP_AT + (wn * 64) * 144 + lmrow * 144 + lmcol * 16;

    float acc[8][4];
#pragma unroll
    for (int j = 0; j < 8; j++)
#pragma unroll
        for (int k = 0; k < 4; k++) acc[j][k] = 0.f;

#pragma unroll
    for (int j = 0; j < 8; j++) {
        uint32_t bj = bbase + j * 8 * 144;
        uint32_t m0, m1, m2, m3, m4, m5, m6, m7;
        ldsm4(m0, m1, m2, m3, bj);
        ldsm4(m4, m5, m6, m7, bj + 64);
        mma_f16(acc[j][0], acc[j][1], acc[j][2], acc[j][3],
                qa[0][0], qa[0][1], qa[0][2], qa[0][3], m0, m1,
                acc[j][0], acc[j][1], acc[j][2], acc[j][3]);
        mma_f16(acc[j][0], acc[j][1], acc[j][2], acc[j][3],
                qa[1][0], qa[1][1], qa[1][2], qa[1][3], m2, m3,
                acc[j][0], acc[j][1], acc[j][2], acc[j][3]);
        mma_f16(acc[j][0], acc[j][1], acc[j][2], acc[j][3],
                qa[2][0], qa[2][1], qa[2][2], qa[2][3], m4, m5,
                acc[j][0], acc[j][1], acc[j][2], acc[j][3]);
        mma_f16(acc[j][0], acc[j][1], acc[j][2], acc[j][3],
                qa[3][0], qa[3][1], qa[3][2], qa[3][3], m6, m7,
                acc[j][0], acc[j][1], acc[j][2], acc[j][3]);
    }

    // staging aliases the fragment region — all frags consumed above
    __syncthreads();
    float* st = (float*)smem;   // [64][132]
    int cl = wc * 16 + g;
#pragma unroll
    for (int j = 0; j < 8; j++) {
        int nl = wn * 64 + 8 * j + 2 * t;
        st[cl * 132 + nl] = acc[j][0];
        st[cl * 132 + nl + 1] = acc[j][1];
        st[(cl + 8) * 132 + nl] = acc[j][2];
        st[(cl + 8) * 132 + nl + 1] = acc[j][3];
    }
    __syncthreads();

#pragma unroll 2
    for (int it = 0; it < 8; it++) {
        int idx = tid + it * 256;
        int c = idx >> 5, n4 = (idx & 31) * 4;
        size_t gi = ((size_t)b * C + c0 + c) * HW + n0 + n4;
        float bi = bo[c0 + c];
        float4 xr = *(const float4*)&x[gi];
        float4 s4 = *(const float4*)&st[c * 132 + n4];
        float4 r;
        r.x = s4.x + bi + xr.x;
        r.y = s4.y + bi + xr.y;
        r.z = s4.z + bi + xr.z;
        r.w = s4.w + bi + xr.w;
        *(float4*)&out[gi] = r;
    }
}

// ---------------------------------------------------------------------------
extern "C" void kernel_launch(void* const* d_in, const int* in_sizes, int n_in,
                              void* d_out, int out_size) {
    const float* x     = (const float*)d_in[0];
    const float* gamma = (const float*)d_in[1];
    const float* beta  = (const float*)d_in[2];
    const float* wq    = (const float*)d_in[3];
    const float* bq    = (const float*)d_in[4];
    const float* wk    = (const float*)d_in[5];
    const float* bk    = (const float*)d_in[6];
    const float* wv    = (const float*)d_in[7];
    const float* bv    = (const float*)d_in[8];
    const float* wo    = (const float*)d_in[9];
    const float* bo    = (const float*)d_in[10];
    float* out = (float*)d_out;

    static int attr_done = 0;
    if (!attr_done) {
        cudaFuncSetAttribute(attn_kernel, cudaFuncAttributeMaxDynamicSharedMemorySize,
                             ATTN_SMEM);
        cudaFuncSetAttribute(proj_kernel, cudaFuncAttributeMaxDynamicSharedMemorySize,
                             PROJ_SMEM);
        cudaFuncSetAttribute(outproj_kernel, cudaFuncAttributeMaxDynamicSharedMemorySize,
                             OUTP_SMEM);
        attr_done = 1;
    }

    gn_fused_kernel<<<BB * GROUPS + 16, 512>>>(x, gamma, beta, wq, wk, wv, wo);
    proj_kernel<<<dim3(HW / 128, BB), 384, PROJ_SMEM>>>(bq, bk, bv);
    attn_kernel<<<dim3(HW / 128, BB), 256, ATTN_SMEM>>>();
    outproj_kernel<<<dim3(HW / 128, C / 64, BB), 256, OUTP_SMEM>>>(x, bo, out);
}

// round 9
// speedup vs baseline: 13.5225x; 1.0191x over previous
#include <cuda_runtime.h>
#include <cuda_fp16.h>
#include <cstdint>

#define BB 4
#define C 512
#define D 64
#define HW 4096
#define GROUPS 32
#define CPG 16
#define EPS 1e-5f

// Scratch (device globals — no allocation allowed)
__device__ __half g_xh[BB * HW * C];     // normalized x, transposed [B,N,C] fp16
__device__ __half g_wqh[D * C], g_wkh[D * C], g_wvh[D * C], g_woh[C * D];
__device__ __half g_qh[BB * HW * D];     // [B,N,D] fp16, pre-scaled by 0.125*log2e
__device__ __half g_kh[BB * HW * D];     // [B,N,D] fp16
__device__ __half g_vth[BB * D * HW];    // [B,D,N] fp16

// ---------------------------------------------------------------------------
// helpers
// ---------------------------------------------------------------------------
__device__ __forceinline__ uint32_t smem_u32(const void* p) {
    uint32_t a;
    asm("{ .reg .u64 t; cvta.to.shared.u64 t, %1; cvt.u32.u64 %0, t; }" : "=r"(a) : "l"(p));
    return a;
}
__device__ __forceinline__ void cp16(uint32_t s, const void* g) {
    asm volatile("cp.async.cg.shared.global [%0], [%1], 16;" :: "r"(s), "l"(g));
}
__device__ __forceinline__ void cp_commit() { asm volatile("cp.async.commit_group;"); }
__device__ __forceinline__ void cp_wait0() { asm volatile("cp.async.wait_group 0;" ::: "memory"); }

__device__ __forceinline__ void mma_f16(float& d0, float& d1, float& d2, float& d3,
                                        uint32_t a0, uint32_t a1, uint32_t a2, uint32_t a3,
                                        uint32_t b0, uint32_t b1,
                                        float c0, float c1, float c2, float c3) {
    asm volatile(
        "mma.sync.aligned.m16n8k16.row.col.f32.f16.f16.f32 "
        "{%0,%1,%2,%3},{%4,%5,%6,%7},{%8,%9},{%10,%11,%12,%13};"
        : "=f"(d0), "=f"(d1), "=f"(d2), "=f"(d3)
        : "r"(a0), "r"(a1), "r"(a2), "r"(a3), "r"(b0), "r"(b1),
          "f"(c0), "f"(c1), "f"(c2), "f"(c3));
}
__device__ __forceinline__ void ldsm4(uint32_t& r0, uint32_t& r1, uint32_t& r2, uint32_t& r3,
                                      uint32_t addr) {
    asm volatile("ldmatrix.sync.aligned.m8n8.x4.shared.b16 {%0,%1,%2,%3}, [%4];"
                 : "=r"(r0), "=r"(r1), "=r"(r2), "=r"(r3) : "r"(addr));
}
__device__ __forceinline__ uint32_t packh2(float lo, float hi) {
    __half2 h = __floats2half2_rn(lo, hi);
    return *(uint32_t*)&h;
}
__device__ __forceinline__ uint32_t ex2_h2(float lo, float hi) {
    uint32_t s, p;
    asm("cvt.rn.f16x2.f32 %0, %1, %2;" : "=r"(s) : "f"(hi), "f"(lo));
    asm("ex2.approx.f16x2 %0, %1;" : "=r"(p) : "r"(s));
    return p;
}

// ---------------------------------------------------------------------------
// 1. Fused GroupNorm (stats + apply + transpose to fp16) and weight convert.
// ---------------------------------------------------------------------------
__global__ void __launch_bounds__(512) gn_fused_kernel(
        const float* __restrict__ x,
        const float* __restrict__ gamma, const float* __restrict__ beta,
        const float* __restrict__ wq, const float* __restrict__ wk,
        const float* __restrict__ wv, const float* __restrict__ wo) {
    int tid = threadIdx.x;
    if (blockIdx.x >= BB * GROUPS) {
        int id = ((blockIdx.x - BB * GROUPS) * 512 + tid) * 4;
        float4 a;
        a = *(const float4*)&wq[id];
        *(__half2*)&g_wqh[id] = __floats2half2_rn(a.x, a.y);
        *(__half2*)&g_wqh[id + 2] = __floats2half2_rn(a.z, a.w);
        a = *(const float4*)&wk[id];
        *(__half2*)&g_wkh[id] = __floats2half2_rn(a.x, a.y);
        *(__half2*)&g_wkh[id + 2] = __floats2half2_rn(a.z, a.w);
        a = *(const float4*)&wv[id];
        *(__half2*)&g_wvh[id] = __floats2half2_rn(a.x, a.y);
        *(__half2*)&g_wvh[id + 2] = __floats2half2_rn(a.z, a.w);
        a = *(const float4*)&wo[id];
        *(__half2*)&g_woh[id] = __floats2half2_rn(a.x, a.y);
        *(__half2*)&g_woh[id + 2] = __floats2half2_rn(a.z, a.w);
        return;
    }

    int bg = blockIdx.x;
    int b = bg / GROUPS, g = bg % GROUPS;
    const float* xp = x + ((size_t)b * C + g * CPG) * HW;
    const int NE = CPG * HW;

    float s = 0.f, ss = 0.f;
    for (int i = tid * 4; i < NE; i += 512 * 4) {
        float4 v = *(const float4*)(xp + i);
        s += v.x + v.y + v.z + v.w;
        ss += v.x * v.x + v.y * v.y + v.z * v.z + v.w * v.w;
    }
    __shared__ float sbuf[32], ssbuf[32];
    __shared__ float sga[CPG], sbe[CPG];
#pragma unroll
    for (int o = 16; o; o >>= 1) {
        s += __shfl_xor_sync(~0u, s, o);
        ss += __shfl_xor_sync(~0u, ss, o);
    }
    int w = tid >> 5;
    if ((tid & 31) == 0) { sbuf[w] = s; ssbuf[w] = ss; }
    __syncthreads();
    if (tid < 32) {
        s = tid < 16 ? sbuf[tid] : 0.f;
        ss = tid < 16 ? ssbuf[tid] : 0.f;
#pragma unroll
        for (int o = 8; o; o >>= 1) {
            s += __shfl_xor_sync(~0u, s, o);
            ss += __shfl_xor_sync(~0u, ss, o);
        }
        if (tid == 0) { sbuf[0] = s; ssbuf[0] = ss; }
    }
    __syncthreads();
    float mean = sbuf[0] / NE;
    float var = ssbuf[0] / NE - mean * mean;
    float rstd = rsqrtf(var + EPS);

    if (tid < CPG) {
        int c = g * CPG + tid;
        float ga = gamma[c] * rstd;
        sga[tid] = ga;
        sbe[tid] = beta[c] - mean * ga;
    }
    __syncthreads();

    float lga[CPG], lbe[CPG];
#pragma unroll
    for (int c = 0; c < CPG; c++) { lga[c] = sga[c]; lbe[c] = sbe[c]; }

    for (int n0i = tid * 4; n0i < HW; n0i += 512 * 4) {
        __align__(16) __half tmp[4][CPG];
#pragma unroll
        for (int c = 0; c < CPG; c++) {
            float4 v = *(const float4*)&xp[(size_t)c * HW + n0i];
            tmp[0][c] = __float2half(v.x * lga[c] + lbe[c]);
            tmp[1][c] = __float2half(v.y * lga[c] + lbe[c]);
            tmp[2][c] = __float2half(v.z * lga[c] + lbe[c]);
            tmp[3][c] = __float2half(v.w * lga[c] + lbe[c]);
        }
#pragma unroll
        for (int k = 0; k < 4; k++) {
            __half* dst = g_xh + ((size_t)b * HW + n0i + k) * C + g * CPG;
            ((uint4*)dst)[0] = ((const uint4*)tmp[k])[0];
            ((uint4*)dst)[1] = ((const uint4*)tmp[k])[1];
        }
    }
}

// ---------------------------------------------------------------------------
// 2. Fused QKV projection via fp16 MMA. 384 threads / 12 warps (unchanged R8).
// ---------------------------------------------------------------------------
#define PJ_XT 0
#define PJ_XBUF 18432
#define PJ_WT 36864
#define PJ_WBUF 27648
#define PROJ_SMEM 92160

__global__ void __launch_bounds__(384, 1) proj_kernel(
        const float* __restrict__ bq, const float* __restrict__ bk,
        const float* __restrict__ bv) {
    extern __shared__ char smem[];
    const uint32_t sb = smem_u32(smem);
    const int tid = threadIdx.x, wid = tid >> 5, lane = tid & 31;
    const int g = lane >> 2, t = lane & 3;
    const int o = wid >> 2, mt = wid & 3;
    const int b = blockIdx.y;
    const int n0 = blockIdx.x * 128;
    const __half* xb = g_xh + (size_t)(b * HW + n0) * C;

    for (int i = tid; i < 1024; i += 384) {
        int r = i >> 3, ch = i & 7;
        cp16(sb + PJ_XT + r * 144 + ch * 16, xb + (size_t)r * C + ch * 8);
    }
    for (int i = tid; i < 1536; i += 384) {
        int r = i >> 3, ch = i & 7;
        const __half* wsrc = (r < 64) ? g_wqh : (r < 128) ? g_wkh : g_wvh;
        int rr = r & 63;
        cp16(sb + PJ_WT + r * 144 + ch * 16, wsrc + rr * C + ch * 8);
    }
    cp_commit();
    cp_wait0();
    __syncthreads();

    float acc[2][8][4];
#pragma unroll
    for (int s = 0; s < 2; s++)
#pragma unroll
        for (int j = 0; j < 8; j++)
#pragma unroll
            for (int k = 0; k < 4; k++) acc[s][j][k] = 0.f;

    const uint32_t lmrow = (lane & 7), lmcol = (lane >> 3);

    for (int kc = 0; kc < 8; kc++) {
        int buf = kc & 1;
        if (kc < 7) {
            int k1 = (kc + 1) * 64;
            int nb = buf ^ 1;
            for (int i = tid; i < 1024; i += 384) {
                int r = i >> 3, ch = i & 7;
                cp16(sb + PJ_XT + nb * PJ_XBUF + r * 144 + ch * 16,
                     xb + (size_t)r * C + k1 + ch * 8);
            }
            for (int i = tid; i < 1536; i += 384) {
                int r = i >> 3, ch = i & 7;
                const __half* wsrc = (r < 64) ? g_wqh : (r < 128) ? g_wkh : g_wvh;
                int rr = r & 63;
                cp16(sb + PJ_WT + nb * PJ_WBUF + r * 144 + ch * 16,
                     wsrc + rr * C + k1 + ch * 8);
            }
        }
        cp_commit();

        uint32_t qa[2][4][4];
#pragma unroll
        for (int s = 0; s < 2; s++) {
            const char* ab = smem + PJ_XT + buf * PJ_XBUF +
                             (mt * 32 + s * 16 + g) * 144 + t * 4;
#pragma unroll
            for (int ks = 0; ks < 4; ks++) {
                qa[s][ks][0] = *(const uint32_t*)(ab + ks * 32);
                qa[s][ks][1] = *(const uint32_t*)(ab + 8 * 144 + ks * 32);
                qa[s][ks][2] = *(const uint32_t*)(ab + ks * 32 + 16);
                qa[s][ks][3] = *(const uint32_t*)(ab + 8 * 144 + ks * 32 + 16);
            }
        }
        uint32_t wbase = sb + PJ_WT + buf * PJ_WBUF + o * 64 * 144 +
                         lmrow * 144 + lmcol * 16;
#pragma unroll
        for (int j = 0; j < 8; j++) {
            uint32_t m0, m1, m2, m3, m4, m5, m6, m7;
            ldsm4(m0, m1, m2, m3, wbase + j * 8 * 144);
            ldsm4(m4, m5, m6, m7, wbase + j * 8 * 144 + 64);
#pragma unroll
            for (int s = 0; s < 2; s++) {
                mma_f16(acc[s][j][0], acc[s][j][1], acc[s][j][2], acc[s][j][3],
                        qa[s][0][0], qa[s][0][1], qa[s][0][2], qa[s][0][3], m0, m1,
                        acc[s][j][0], acc[s][j][1], acc[s][j][2], acc[s][j][3]);
                mma_f16(acc[s][j][0], acc[s][j][1], acc[s][j][2], acc[s][j][3],
                        qa[s][1][0], qa[s][1][1], qa[s][1][2], qa[s][1][3], m2, m3,
                        acc[s][j][0], acc[s][j][1], acc[s][j][2], acc[s][j][3]);
                mma_f16(acc[s][j][0], acc[s][j][1], acc[s][j][2], acc[s][j][3],
                        qa[s][2][0], qa[s][2][1], qa[s][2][2], qa[s][2][3], m4, m5,
                        acc[s][j][0], acc[s][j][1], acc[s][j][2], acc[s][j][3]);
                mma_f16(acc[s][j][0], acc[s][j][1], acc[s][j][2], acc[s][j][3],
                        qa[s][3][0], qa[s][3][1], qa[s][3][2], qa[s][3][3], m6, m7,
                        acc[s][j][0], acc[s][j][1], acc[s][j][2], acc[s][j][3]);
            }
        }
        if (kc < 7) {
            cp_wait0();
            __syncthreads();
        }
    }

    const float QSC = 0.125f * 1.44269504f;
    if (o == 0) {
        __half* outp = g_qh + (size_t)(b * HW + n0) * D;
#pragma unroll
        for (int s = 0; s < 2; s++) {
            int nloc = mt * 32 + s * 16 + g;
#pragma unroll
            for (int j = 0; j < 8; j++) {
                int d0 = 8 * j + 2 * t;
                float b0v = bq[d0], b1v = bq[d0 + 1];
                *(uint32_t*)&outp[(size_t)nloc * D + d0] =
                    packh2((acc[s][j][0] + b0v) * QSC, (acc[s][j][1] + b1v) * QSC);
                *(uint32_t*)&outp[(size_t)(nloc + 8) * D + d0] =
                    packh2((acc[s][j][2] + b0v) * QSC, (acc[s][j][3] + b1v) * QSC);
            }
        }
    } else if (o == 1) {
        __half* outp = g_kh + (size_t)(b * HW + n0) * D;
#pragma unroll
        for (int s = 0; s < 2; s++) {
            int nloc = mt * 32 + s * 16 + g;
#pragma unroll
            for (int j = 0; j < 8; j++) {
                int d0 = 8 * j + 2 * t;
                float b0v = bk[d0], b1v = bk[d0 + 1];
                *(uint32_t*)&outp[(size_t)nloc * D + d0] =
                    packh2(acc[s][j][0] + b0v, acc[s][j][1] + b1v);
                *(uint32_t*)&outp[(size_t)(nloc + 8) * D + d0] =
                    packh2(acc[s][j][2] + b0v, acc[s][j][3] + b1v);
            }
        }
    }
    __syncthreads();
    __half* vst = (__half*)smem;  // [64][136]
    if (o == 2) {
#pragma unroll
        for (int s = 0; s < 2; s++) {
            int nloc = mt * 32 + s * 16 + g;
#pragma unroll
            for (int j = 0; j < 8; j++) {
                int d0 = 8 * j + 2 * t;
                float b0v = bv[d0], b1v = bv[d0 + 1];
                vst[d0 * 136 + nloc] = __float2half(acc[s][j][0] + b0v);
                vst[(d0 + 1) * 136 + nloc] = __float2half(acc[s][j][1] + b1v);
                vst[d0 * 136 + nloc + 8] = __float2half(acc[s][j][2] + b0v);
                vst[(d0 + 1) * 136 + nloc + 8] = __float2half(acc[s][j][3] + b1v);
            }
        }
    }
    __syncthreads();
    for (int i = tid; i < 1024; i += 384) {
        int d = i >> 4, nn = (i & 15) * 8;
        *(uint4*)&g_vth[((size_t)b * D + d) * HW + n0 + nn] =
            *(const uint4*)&vst[d * 136 + nn];
    }
}

// ---------------------------------------------------------------------------
// 3. fp16 mma.sync flash attention FUSED with output projection + residual.
//    After the flash loop: ao (normalized) -> smem fp16; wo streamed in 4
//    chunks of 128 c-rows through the free K double-buffer; per n8 block the
//    result is written straight to out with bias + x residual.
// ---------------------------------------------------------------------------
#define QPITCH 144
#define KPITCH 144
#define VPITCH 272
#define SQ_OFF 0
#define SK_OFF 18432
#define KBYTES 18432
#define SV_OFF (18432 + 2 * 18432)
#define VBYTES (72 * 272)                 // 19584
#define ATTN_SMEM (SV_OFF + 2 * VBYTES)   // 94464

__global__ void __launch_bounds__(256, 1) attn_kernel(
        const float* __restrict__ x,
        const float* __restrict__ bo,
        float* __restrict__ out) {
    extern __shared__ char smem[];
    const uint32_t sb = smem_u32(smem);
    const int tid = threadIdx.x, wid = tid >> 5, lane = tid & 31;
    const int g = lane >> 2, t = lane & 3;
    const int b = blockIdx.y;
    const int n0 = blockIdx.x * 128;

    const __half* qh = g_qh + ((size_t)b * HW + n0) * D;
    const __half* kh = g_kh + (size_t)b * HW * D;
    const __half* vh = g_vth + (size_t)b * D * HW;

    for (int i = tid; i < 1024; i += 256) {
        int r = i >> 3, ch = i & 7;
        cp16(sb + SQ_OFF + r * QPITCH + ch * 16, qh + r * 64 + ch * 8);
    }
    for (int i = tid; i < 1024; i += 256) {
        int r = i >> 3, ch = i & 7;
        cp16(sb + SK_OFF + r * KPITCH + ch * 16, kh + (size_t)r * 64 + ch * 8);
    }
    for (int i = tid; i < 1024; i += 256) {
        int r = i >> 4, ch = i & 15;
        cp16(sb + SV_OFF + r * VPITCH + ch * 16, vh + (size_t)r * HW + ch * 8);
    }
    cp_commit();
    for (int i = tid; i < 2 * 8 * 136; i += 256) {
        int bf = i / 1088, rem = i % 1088;
        int row = 64 + rem / 136, col = rem % 136;
        __half val = (row == 64 && col < 128) ? __float2half(1.f) : __float2half(0.f);
        *(__half*)(smem + SV_OFF + bf * VBYTES + row * VPITCH + col * 2) = val;
    }
    cp_wait0();
    __syncthreads();

    uint32_t qa[4][4];
    {
        const char* qbase = smem + SQ_OFF + (wid * 16 + g) * QPITCH + t * 4;
#pragma unroll
        for (int s = 0; s < 4; s++) {
            qa[s][0] = *(const uint32_t*)(qbase + s * 32);
            qa[s][1] = *(const uint32_t*)(qbase + 8 * QPITCH + s * 32);
            qa[s][2] = *(const uint32_t*)(qbase + s * 32 + 16);
            qa[s][3] = *(const uint32_t*)(qbase + 8 * QPITCH + s * 32 + 16);
        }
    }

    float o[9][4];
#pragma unroll
    for (int j = 0; j < 9; j++)
#pragma unroll
        for (int k = 0; k < 4; k++) o[j][k] = 0.f;

    const uint32_t lmrow = (lane & 7), lmcol = (lane >> 3);

    for (int it = 0; it < 32; it++) {
        int buf = it & 1;

        if (it + 1 < 32) {
            int t1 = (it + 1) * 128;
            int nb = buf ^ 1;
            for (int i = tid; i < 1024; i += 256) {
                int r = i >> 3, ch = i & 7;
                cp16(sb + SK_OFF + nb * KBYTES + r * KPITCH + ch * 16,
                     kh + (size_t)(t1 + r) * 64 + ch * 8);
            }
            for (int i = tid; i < 1024; i += 256) {
                int r = i >> 4, ch = i & 15;
                cp16(sb + SV_OFF + nb * VBYTES + r * VPITCH + ch * 16,
                     vh + (size_t)r * HW + t1 + ch * 8);
            }
        }
        cp_commit();

        uint32_t kaddr = sb + SK_OFF + buf * KBYTES + lmrow * KPITCH + lmcol * 16;
        uint32_t vaddr = sb + SV_OFF + buf * VBYTES + lmrow * VPITCH + lmcol * 16;

        uint32_t pa[8][4];
#pragma unroll
        for (int j = 0; j < 16; j++) {
            float c0 = 0.f, c1 = 0.f, c2 = 0.f, c3 = 0.f;
            uint32_t kj = kaddr + j * 8 * KPITCH;
            uint32_t m0, m1, m2, m3, m4, m5, m6, m7;
            ldsm4(m0, m1, m2, m3, kj);
            ldsm4(m4, m5, m6, m7, kj + 64);
            mma_f16(c0, c1, c2, c3, qa[0][0], qa[0][1], qa[0][2], qa[0][3],
                    m0, m1, c0, c1, c2, c3);
            mma_f16(c0, c1, c2, c3, qa[1][0], qa[1][1], qa[1][2], qa[1][3],
                    m2, m3, c0, c1, c2, c3);
            mma_f16(c0, c1, c2, c3, qa[2][0], qa[2][1], qa[2][2], qa[2][3],
                    m4, m5, c0, c1, c2, c3);
            mma_f16(c0, c1, c2, c3, qa[3][0], qa[3][1], qa[3][2], qa[3][3],
                    m6, m7, c0, c1, c2, c3);
            pa[j >> 1][(j & 1) * 2 + 0] = ex2_h2(c0, c1);
            pa[j >> 1][(j & 1) * 2 + 1] = ex2_h2(c2, c3);
        }

#pragma unroll
        for (int j = 0; j < 9; j++) {
            uint32_t vj = vaddr + j * 8 * VPITCH;
            uint32_t m0, m1, m2, m3;
#pragma unroll
            for (int h = 0; h < 4; h++) {
                ldsm4(m0, m1, m2, m3, vj + h * 64);
                mma_f16(o[j][0], o[j][1], o[j][2], o[j][3],
                        pa[2 * h][0], pa[2 * h][1], pa[2 * h][2], pa[2 * h][3],
                        m0, m1, o[j][0], o[j][1], o[j][2], o[j][3]);
                mma_f16(o[j][0], o[j][1], o[j][2], o[j][3],
                        pa[2 * h + 1][0], pa[2 * h + 1][1], pa[2 * h + 1][2], pa[2 * h + 1][3],
                        m2, m3, o[j][0], o[j][1], o[j][2], o[j][3]);
            }
        }

        if (it + 1 < 32) {
            cp_wait0();
            __syncthreads();
        }
    }

    float l0 = __shfl_sync(~0u, o[8][0], lane & 28);
    float l1 = __shfl_sync(~0u, o[8][2], lane & 28);
    float i0 = 1.f / l0, i1 = 1.f / l1;

    // ---- fused output projection ----
    // Stage normalized ao as fp16 [128 n][64 d], pitch 144, in the Q region.
    __syncthreads();   // all warps done with K/V smem reads
    {
        char* aos = smem + SQ_OFF;
        int nloc = wid * 16 + g;
#pragma unroll
        for (int j = 0; j < 8; j++) {
            int d0 = 8 * j + 2 * t;
            *(uint32_t*)(aos + nloc * 144 + d0 * 2) = packh2(o[j][0] * i0, o[j][1] * i0);
            *(uint32_t*)(aos + (nloc + 8) * 144 + d0 * 2) = packh2(o[j][2] * i1, o[j][3] * i1);
        }
    }
    // chunk 0 of wo into K buffer 0
    for (int i = tid; i < 1024; i += 256) {
        int r = i >> 3, ch = i & 7;
        cp16(sb + SK_OFF + r * 144 + ch * 16, g_woh + (size_t)r * 64 + ch * 8);
    }
    cp_commit();
    cp_wait0();
    __syncthreads();

    for (int cc = 0; cc < 4; cc++) {
        int buf = cc & 1;
        if (cc < 3) {
            int cb1 = (cc + 1) * 128;
            int nb = buf ^ 1;
            for (int i = tid; i < 1024; i += 256) {
                int r = i >> 3, ch = i & 7;
                cp16(sb + SK_OFF + nb * KBYTES + r * 144 + ch * 16,
                     g_woh + (size_t)(cb1 + r) * 64 + ch * 8);
            }
        }
        cp_commit();

        // A-frags: this warp's 16 wo rows (c = cc*128 + wid*16 + g / +8)
        const char* abase = smem + SK_OFF + buf * KBYTES + (wid * 16 + g) * 144 + t * 4;
        uint32_t wa[4][4];
#pragma unroll
        for (int s = 0; s < 4; s++) {
            wa[s][0] = *(const uint32_t*)(abase + s * 32);
            wa[s][1] = *(const uint32_t*)(abase + 8 * 144 + s * 32);
            wa[s][2] = *(const uint32_t*)(abase + s * 32 + 16);
            wa[s][3] = *(const uint32_t*)(abase + 8 * 144 + s * 32 + 16);
        }
        uint32_t bb = sb + SQ_OFF + lmrow * 144 + lmcol * 16;

        int c_row = cc * 128 + wid * 16 + g;
        float bo0 = __ldg(&bo[c_row]);
        float bo1 = __ldg(&bo[c_row + 8]);
        const float* xr = x + ((size_t)b * C + c_row) * HW + n0;
        float* outr = out + ((size_t)b * C + c_row) * HW + n0;

#pragma unroll
        for (int j = 0; j < 16; j++) {
            uint32_t bj = bb + j * 8 * 144;
            uint32_t m0, m1, m2, m3, m4, m5, m6, m7;
            ldsm4(m0, m1, m2, m3, bj);
            ldsm4(m4, m5, m6, m7, bj + 64);
            float a0 = 0.f, a1 = 0.f, a2 = 0.f, a3 = 0.f;
            mma_f16(a0, a1, a2, a3, wa[0][0], wa[0][1], wa[0][2], wa[0][3],
                    m0, m1, a0, a1, a2, a3);
            mma_f16(a0, a1, a2, a3, wa[1][0], wa[1][1], wa[1][2], wa[1][3],
                    m2, m3, a0, a1, a2, a3);
            mma_f16(a0, a1, a2, a3, wa[2][0], wa[2][1], wa[2][2], wa[2][3],
                    m4, m5, a0, a1, a2, a3);
            mma_f16(a0, a1, a2, a3, wa[3][0], wa[3][1], wa[3][2], wa[3][3],
                    m6, m7, a0, a1, a2, a3);
            int nl = 8 * j + 2 * t;
            float2 xv0 = *(const float2*)(xr + nl);
            float2 xv1 = *(const float2*)(xr + 8 * HW + nl);
            float2 r0 = {a0 + bo0 + xv0.x, a1 + bo0 + xv0.y};
            float2 r1 = {a2 + bo1 + xv1.x, a3 + bo1 + xv1.y};
            *(float2*)(outr + nl) = r0;
            *(float2*)(outr + 8 * HW + nl) = r1;
        }

        if (cc < 3) {
            cp_wait0();
            __syncthreads();
        }
    }
}

// ---------------------------------------------------------------------------
extern "C" void kernel_launch(void* const* d_in, const int* in_sizes, int n_in,
                              void* d_out, int out_size) {
    const float* x     = (const float*)d_in[0];
    const float* gamma = (const float*)d_in[1];
    const float* beta  = (const float*)d_in[2];
    const float* wq    = (const float*)d_in[3];
    const float* bq    = (const float*)d_in[4];
    const float* wk    = (const float*)d_in[5];
    const float* bk    = (const float*)d_in[6];
    const float* wv    = (const float*)d_in[7];
    const float* bv    = (const float*)d_in[8];
    const float* wo    = (const float*)d_in[9];
    const float* bo    = (const float*)d_in[10];
    float* out = (float*)d_out;

    static int attr_done = 0;
    if (!attr_done) {
        cudaFuncSetAttribute(attn_kernel, cudaFuncAttributeMaxDynamicSharedMemorySize,
                             ATTN_SMEM);
        cudaFuncSetAttribute(proj_kernel, cudaFuncAttributeMaxDynamicSharedMemorySize,
                             PROJ_SMEM);
        attr_done = 1;
    }

    gn_fused_kernel<<<BB * GROUPS + 16, 512>>>(x, gamma, beta, wq, wk, wv, wo);
    proj_kernel<<<dim3(HW / 128, BB), 384, PROJ_SMEM>>>(bq, bk, bv);
    attn_kernel<<<dim3(HW / 128, BB), 256, ATTN_SMEM>>>(x, bo, out);
}